// round 14
// baseline (speedup 1.0000x reference)
#include <cuda_runtime.h>
#include <cuda_fp16.h>
#include <cstdint>

// Problem constants
#define BB 4
#define SS 1024
#define KK 1024
#define DD 1024
#define HH 16
#define HD 64
#define MRD 4096
#define SIXD 6144
#define NBS 4096
#define INV_SQRT_HD 0.125f
#define GELU_C 0.7978845608028654f

// ---------------- scratch ----------------
__device__ __align__(16) float  g_mod[BB * SIXD];
__device__ __align__(16) float  g_x[NBS * DD];
__device__ __align__(16) __half g_qn_h[NBS * DD];
__device__ __align__(16) __half g_kvn_h[NBS * DD];
__device__ __align__(16) __half g_q_h[NBS * DD];
__device__ __align__(16) __half g_kv_h[NBS * 2 * DD];
__device__ __align__(16) __half g_attn_h[NBS * DD];
__device__ __align__(16) __half g_hh[NBS * DD];
__device__ __align__(16) __half g_h1_h[(size_t)NBS * MRD];
__device__ __align__(16) __half g_wq_h[DD * DD];
__device__ __align__(16) __half g_wkv_h[DD * 2 * DD];
__device__ __align__(16) __half g_wo_h[DD * DD];
__device__ __align__(16) __half g_w1_h[DD * MRD];
__device__ __align__(16) __half g_w2_h[MRD * DD];
__device__ int    g_enIsByte;

// ================= PTX helpers =================
__device__ __forceinline__ uint32_t smem_u32(const void* p) {
    uint32_t a;
    asm("{ .reg .u64 t; cvta.to.shared.u64 t, %1; cvt.u32.u64 %0, t; }" : "=r"(a) : "l"(p));
    return a;
}
#define CP_ASYNC16(sa, ga) \
    asm volatile("cp.async.ca.shared.global [%0], [%1], 16;" :: "r"(sa), "l"(ga) : "memory")
#define CP_COMMIT() asm volatile("cp.async.commit_group;" ::: "memory")
#define CP_WAIT0()  asm volatile("cp.async.wait_group 0;" ::: "memory")
#define CP_WAIT1()  asm volatile("cp.async.wait_group 1;" ::: "memory")
#define CP_WAIT2()  asm volatile("cp.async.wait_group 2;" ::: "memory")

#define LDSM_X4(d0, d1, d2, d3, addr)                                          \
    asm volatile("ldmatrix.sync.aligned.m8n8.x4.shared.b16 {%0,%1,%2,%3}, [%4];" \
        : "=r"(d0), "=r"(d1), "=r"(d2), "=r"(d3) : "r"(addr))
#define LDSM_X4_T(d0, d1, d2, d3, addr)                                        \
    asm volatile("ldmatrix.sync.aligned.m8n8.x4.trans.shared.b16 {%0,%1,%2,%3}, [%4];" \
        : "=r"(d0), "=r"(d1), "=r"(d2), "=r"(d3) : "r"(addr))

__device__ __forceinline__ void mma_f16(float* c, uint32_t a0, uint32_t a1,
                                        uint32_t a2, uint32_t a3,
                                        uint32_t b0, uint32_t b1) {
    asm volatile(
        "mma.sync.aligned.m16n8k16.row.col.f32.f16.f16.f32 "
        "{%0,%1,%2,%3}, {%4,%5,%6,%7}, {%8,%9}, {%0,%1,%2,%3};"
        : "+f"(c[0]), "+f"(c[1]), "+f"(c[2]), "+f"(c[3])
        : "r"(a0), "r"(a1), "r"(a2), "r"(a3), "r"(b0), "r"(b1));
}
__device__ __forceinline__ float gelu_f(float v) {
    float u = GELU_C * (v + 0.044715f * v * v * v);
    u = fminf(fmaxf(u, -15.f), 15.f);
    float t = __expf(2.0f * u);
    return 0.5f * v * (1.0f + (t - 1.0f) / (t + 1.0f));
}

// ====== fp16 mma GEMM: occ-1, 4-stage cp.async ring, single sync/iter, =======
// ====== fragment double buffering across kt steps.                     =======
#define KPA 72
#define BPB 136
#define ASTG (128 * KPA)    // 9216 halves
#define BSTG (64 * BPB)     // 8704 halves
#define NSTAGE 4
#define GSM_BYTES (NSTAGE * (ASTG + BSTG) * 2)   // 143360 bytes

template <int EPI>
__global__ void __launch_bounds__(256, 1) gemm_h(
    const __half* __restrict__ A, const __half* __restrict__ B, void* __restrict__ Cv,
    int Kd, int lda, int ldb, int ldc,
    const float* __restrict__ bias, const float* __restrict__ modv, int goff,
    const void* __restrict__ en, const float* __restrict__ basep)
{
    extern __shared__ __half smh[];
    const uint32_t smw = smem_u32(smh);

    const int tid = threadIdx.x;
    const int lane = tid & 31;
    const int wid = tid >> 5;
    const int wm = wid >> 2, wn = wid & 3;
    const int lq = lane >> 2, lr = lane & 3;
    const int rsel = lane & 15;
    const int ksel = (lane >> 4) * 8;

    const int row0 = blockIdx.y * 128, col0 = blockIdx.x * 128;

    float acc[4][4][4];
    #pragma unroll
    for (int i = 0; i < 4; i++)
        #pragma unroll
        for (int j = 0; j < 4; j++)
            #pragma unroll
            for (int e = 0; e < 4; e++) acc[i][j][e] = 0.f;

    const int nk = Kd / 64;

    auto load_stage = [&](int ks) {
        const int k0 = ks * 64;
        const int s = ks & 3;
        uint32_t abase = smw + (uint32_t)s * ASTG * 2;
        #pragma unroll
        for (int j = 0; j < 4; j++) {
            int idx = tid + 256 * j;
            int r = idx >> 3, c = idx & 7;
            CP_ASYNC16(abase + (uint32_t)(r * KPA + c * 8) * 2,
                       A + (size_t)(row0 + r) * lda + k0 + c * 8);
        }
        uint32_t bbase = smw + (uint32_t)(NSTAGE * ASTG + s * BSTG) * 2;
        #pragma unroll
        for (int j = 0; j < 4; j++) {
            int idx = tid + 256 * j;
            int r = idx >> 4, c = idx & 15;
            CP_ASYNC16(bbase + (uint32_t)(r * BPB + c * 8) * 2,
                       B + (size_t)(k0 + r) * ldb + col0 + c * 8);
        }
        CP_COMMIT();
    };

    load_stage(0);
    if (nk > 1) load_stage(1);
    if (nk > 2) load_stage(2);

    // fragment buffers (double-buffered across kt)
    uint32_t af[2][4][4];
    uint32_t bf[2][2][4];

    for (int i = 0; i < nk; i++) {
        const int rem = nk - 1 - i;
        if (rem >= 2) CP_WAIT2(); else if (rem == 1) CP_WAIT1(); else CP_WAIT0();
        __syncthreads();
        if (i + 3 < nk) load_stage(i + 3);   // buffer (i+3)&3 freed by compute(i-1), guarded by sync

        const int s = i & 3;
        const uint32_t abase = smw + (uint32_t)s * ASTG * 2;
        const uint32_t bbase = smw + (uint32_t)(NSTAGE * ASTG + s * BSTG) * 2;

        // preload kt=0 fragments
        #pragma unroll
        for (int mi = 0; mi < 4; mi++) {
            int rm = wm * 64 + mi * 16;
            LDSM_X4(af[0][mi][0], af[0][mi][1], af[0][mi][2], af[0][mi][3],
                    abase + (uint32_t)((rm + rsel) * KPA + ksel) * 2);
        }
        #pragma unroll
        for (int njp = 0; njp < 2; njp++) {
            int n0 = wn * 32 + njp * 16;
            LDSM_X4_T(bf[0][njp][0], bf[0][njp][1], bf[0][njp][2], bf[0][njp][3],
                      bbase + (uint32_t)(rsel * BPB + n0 + ksel) * 2);
        }

        #pragma unroll
        for (int kt = 0; kt < 4; kt++) {
            const int cur = kt & 1, nxt = cur ^ 1;
            if (kt < 3) {
                #pragma unroll
                for (int mi = 0; mi < 4; mi++) {
                    int rm = wm * 64 + mi * 16;
                    LDSM_X4(af[nxt][mi][0], af[nxt][mi][1], af[nxt][mi][2], af[nxt][mi][3],
                            abase + (uint32_t)((rm + rsel) * KPA + (kt + 1) * 16 + ksel) * 2);
                }
                #pragma unroll
                for (int njp = 0; njp < 2; njp++) {
                    int n0 = wn * 32 + njp * 16;
                    LDSM_X4_T(bf[nxt][njp][0], bf[nxt][njp][1], bf[nxt][njp][2], bf[nxt][njp][3],
                              bbase + (uint32_t)(((kt + 1) * 16 + rsel) * BPB + n0 + ksel) * 2);
                }
            }
            #pragma unroll
            for (int njp = 0; njp < 2; njp++) {
                #pragma unroll
                for (int mi = 0; mi < 4; mi++) {
                    mma_f16(acc[mi][2 * njp],     af[cur][mi][0], af[cur][mi][1],
                            af[cur][mi][2], af[cur][mi][3], bf[cur][njp][0], bf[cur][njp][1]);
                    mma_f16(acc[mi][2 * njp + 1], af[cur][mi][0], af[cur][mi][1],
                            af[cur][mi][2], af[cur][mi][3], bf[cur][njp][2], bf[cur][njp][3]);
                }
            }
        }
    }

    #pragma unroll
    for (int mi = 0; mi < 4; mi++) {
        int rg = row0 + wm * 64 + mi * 16 + lq;
        float g0 = 0.f, g1 = 0.f;
        if (EPI == 2) {
            int e0 = g_enIsByte ? (int)((const unsigned char*)en)[rg] : ((const int*)en)[rg];
            int e1 = g_enIsByte ? (int)((const unsigned char*)en)[rg + 8] : ((const int*)en)[rg + 8];
            g0 = e0 ? 1.f : 0.f;
            g1 = e1 ? 1.f : 0.f;
        }
        #pragma unroll
        for (int nj = 0; nj < 4; nj++) {
            int cg = col0 + wn * 32 + nj * 8 + lr * 2;
            float v0 = acc[mi][nj][0], v1 = acc[mi][nj][1];
            float v2 = acc[mi][nj][2], v3 = acc[mi][nj][3];
            if (EPI == 0) {
                __half* C = (__half*)Cv;
                *(half2*)(C + (size_t)rg * ldc + cg) = __floats2half2_rn(v0, v1);
                *(half2*)(C + (size_t)(rg + 8) * ldc + cg) = __floats2half2_rn(v2, v3);
            } else if (EPI == 1) {
                float b0 = bias[cg], b1v = bias[cg + 1];
                __half* C = (__half*)Cv;
                *(half2*)(C + (size_t)rg * ldc + cg) =
                    __floats2half2_rn(gelu_f(v0 + b0), gelu_f(v1 + b1v));
                *(half2*)(C + (size_t)(rg + 8) * ldc + cg) =
                    __floats2half2_rn(gelu_f(v2 + b0), gelu_f(v3 + b1v));
            } else {
                float b0 = bias ? bias[cg] : 0.f, b1v = bias ? bias[cg + 1] : 0.f;
                int bb0 = rg >> 10, bb1 = (rg + 8) >> 10;
                float m00 = modv[bb0 * SIXD + goff + cg];
                float m01 = modv[bb0 * SIXD + goff + cg + 1];
                float m10 = modv[bb1 * SIXD + goff + cg];
                float m11 = modv[bb1 * SIXD + goff + cg + 1];
                float* C = (float*)Cv;
                *(float2*)(C + (size_t)rg * ldc + cg) = make_float2(
                    basep[(size_t)rg * DD + cg] + g0 * m00 * (v0 + b0),
                    basep[(size_t)rg * DD + cg + 1] + g0 * m01 * (v1 + b1v));
                *(float2*)(C + (size_t)(rg + 8) * ldc + cg) = make_float2(
                    basep[(size_t)(rg + 8) * DD + cg] + g1 * m10 * (v2 + b0),
                    basep[(size_t)(rg + 8) * DD + cg + 1] + g1 * m11 * (v3 + b1v));
            }
        }
    }
}

// ================= flash attention (fp16 mma, fused RoPE, occ-2) — unchanged R12 =================
#define FQP 72
#define FPP 136
#define FKO 9216
#define FVO 18432
#define FPO 27648
#define FL_BYTES (45056 * 2 + 1024)

__global__ void __launch_bounds__(256, 2) flash_h(
    const __half* __restrict__ q, const __half* __restrict__ kv,
    const int* __restrict__ grp, __half* __restrict__ attn,
    const float* __restrict__ cosq, const float* __restrict__ sinq,
    const float* __restrict__ cosk, const float* __restrict__ sink)
{
    extern __shared__ __half smh[];
    const uint32_t smw = smem_u32(smh);
    int* grpq = (int*)(smh + 45056);
    int* grpk = grpq + 128;

    const int tid = threadIdx.x;
    const int lane = tid & 31;
    const int wid = tid >> 5;
    const int wr0 = wid * 16;
    const int lq = lane >> 2, lr = lane & 3;
    const int rsel = lane & 15;
    const int ksel = (lane >> 4) * 8;
    const int nsel = (lane & 7) + (lane >> 4) * 8;
    const int kse2 = ((lane >> 3) & 1) * 8;

    const int qb = blockIdx.x;
    const int b = blockIdx.y >> 4;
    const int h = blockIdx.y & 15;

    #pragma unroll
    for (int j = 0; j < 4; j++) {
        int idx = tid + 256 * j;
        int r = idx >> 3, c8 = idx & 7;
        int s = qb * 128 + r;
        const __half* row = q + (size_t)(b * SS + s) * DD + h * HD;
        uint4 own = *(const uint4*)(row + 8 * c8);
        uint4 par = *(const uint4*)(row + 8 * (c8 ^ 4));
        const __half* oh = (const __half*)&own;
        const __half* ph = (const __half*)&par;
        float4 cz0 = *(const float4*)(cosq + s * HD + 8 * c8);
        float4 cz1 = *(const float4*)(cosq + s * HD + 8 * c8 + 4);
        float4 sz0 = *(const float4*)(sinq + s * HD + 8 * c8);
        float4 sz1 = *(const float4*)(sinq + s * HD + 8 * c8 + 4);
        float czv[8] = {cz0.x, cz0.y, cz0.z, cz0.w, cz1.x, cz1.y, cz1.z, cz1.w};
        float szv[8] = {sz0.x, sz0.y, sz0.z, sz0.w, sz1.x, sz1.y, sz1.z, sz1.w};
        float sgn = (c8 & 4) ? 1.f : -1.f;
        __half res[8];
        #pragma unroll
        for (int e = 0; e < 8; e++) {
            float x1 = __half2float(oh[e]);
            float x2 = __half2float(ph[e]);
            res[e] = __float2half_rn(x1 * czv[e] + sgn * x2 * szv[e]);
        }
        *(uint4*)(smh + r * FQP + 8 * c8) = *(uint4*)res;
    }
    if (tid < 128) grpq[tid] = grp[b * 1024 + qb * 128 + tid];

    float m0 = -3.0e38f, m1 = -3.0e38f, l0 = 0.f, l1 = 0.f;
    float oacc[8][4];
    #pragma unroll
    for (int j = 0; j < 8; j++)
        #pragma unroll
        for (int e = 0; e < 4; e++) oacc[j][e] = 0.f;

    for (int kc = 0; kc < 8; kc++) {
        #pragma unroll
        for (int j = 0; j < 4; j++) {
            int idx = tid + 256 * j;
            int r = idx >> 3, c = idx & 7;
            CP_ASYNC16(smw + (uint32_t)(FVO + r * FQP + c * 8) * 2,
                       kv + (size_t)(b * 1024 + kc * 128 + r) * (2 * DD) + DD + h * HD + c * 8);
        }
        CP_COMMIT();
        #pragma unroll
        for (int j = 0; j < 4; j++) {
            int idx = tid + 256 * j;
            int r = idx >> 3, c8 = idx & 7;
            int s = kc * 128 + r;
            const __half* row = kv + (size_t)(b * 1024 + s) * (2 * DD) + h * HD;
            uint4 own = *(const uint4*)(row + 8 * c8);
            uint4 par = *(const uint4*)(row + 8 * (c8 ^ 4));
            const __half* oh = (const __half*)&own;
            const __half* ph = (const __half*)&par;
            float4 cz0 = *(const float4*)(cosk + s * HD + 8 * c8);
            float4 cz1 = *(const float4*)(cosk + s * HD + 8 * c8 + 4);
            float4 sz0 = *(const float4*)(sink + s * HD + 8 * c8);
            float4 sz1 = *(const float4*)(sink + s * HD + 8 * c8 + 4);
            float czv[8] = {cz0.x, cz0.y, cz0.z, cz0.w, cz1.x, cz1.y, cz1.z, cz1.w};
            float szv[8] = {sz0.x, sz0.y, sz0.z, sz0.w, sz1.x, sz1.y, sz1.z, sz1.w};
            float sgn = (c8 & 4) ? 1.f : -1.f;
            __half res[8];
            #pragma unroll
            for (int e = 0; e < 8; e++) {
                float x1 = __half2float(oh[e]);
                float x2 = __half2float(ph[e]);
                res[e] = __float2half_rn(x1 * czv[e] + sgn * x2 * szv[e]);
            }
            *(uint4*)(smh + FKO + r * FQP + 8 * c8) = *(uint4*)res;
        }
        if (tid < 128) grpk[tid] = grp[b * 1024 + kc * 128 + tid];
        CP_WAIT0();
        __syncthreads();

        float sacc[16][4];
        #pragma unroll
        for (int nj = 0; nj < 16; nj++)
            #pragma unroll
            for (int e = 0; e < 4; e++) sacc[nj][e] = 0.f;

        #pragma unroll
        for (int kt = 0; kt < 4; kt++) {
            uint32_t a0, a1, a2, a3;
            LDSM_X4(a0, a1, a2, a3,
                    smw + (uint32_t)((wr0 + rsel) * FQP + kt * 16 + ksel) * 2);
            #pragma unroll
            for (int njp = 0; njp < 8; njp++) {
                uint32_t b0, b1, b2, b3;
                LDSM_X4(b0, b1, b2, b3,
                        smw + (uint32_t)(FKO + (njp * 16 + nsel) * FQP + kt * 16 + kse2) * 2);
                mma_f16(sacc[2 * njp],     a0, a1, a2, a3, b0, b1);
                mma_f16(sacc[2 * njp + 1], a0, a1, a2, a3, b2, b3);
            }
        }

        int gq0 = grpq[wr0 + lq], gq1 = grpq[wr0 + lq + 8];
        float rm0 = -3.0e38f, rm1 = -3.0e38f;
        #pragma unroll
        for (int nj = 0; nj < 16; nj++) {
            int c0i = nj * 8 + 2 * lr;
            int gk0 = grpk[c0i], gk1 = grpk[c0i + 1];
            float s0 = (gk0 != gq0) ? sacc[nj][0] * INV_SQRT_HD : -1.0e9f;
            float s1 = (gk1 != gq0) ? sacc[nj][1] * INV_SQRT_HD : -1.0e9f;
            float s2 = (gk0 != gq1) ? sacc[nj][2] * INV_SQRT_HD : -1.0e9f;
            float s3 = (gk1 != gq1) ? sacc[nj][3] * INV_SQRT_HD : -1.0e9f;
            sacc[nj][0] = s0; sacc[nj][1] = s1; sacc[nj][2] = s2; sacc[nj][3] = s3;
            rm0 = fmaxf(rm0, fmaxf(s0, s1));
            rm1 = fmaxf(rm1, fmaxf(s2, s3));
        }
        rm0 = fmaxf(rm0, __shfl_xor_sync(0xffffffffu, rm0, 1));
        rm0 = fmaxf(rm0, __shfl_xor_sync(0xffffffffu, rm0, 2));
        rm1 = fmaxf(rm1, __shfl_xor_sync(0xffffffffu, rm1, 1));
        rm1 = fmaxf(rm1, __shfl_xor_sync(0xffffffffu, rm1, 2));
        float mn0 = fmaxf(m0, rm0), mn1 = fmaxf(m1, rm1);
        float al0 = __expf(m0 - mn0), al1 = __expf(m1 - mn1);

        __half* Ps = smh + FPO;
        float ps0 = 0.f, ps1 = 0.f;
        #pragma unroll
        for (int nj = 0; nj < 16; nj++) {
            float e0 = __expf(sacc[nj][0] - mn0);
            float e1 = __expf(sacc[nj][1] - mn0);
            float e2 = __expf(sacc[nj][2] - mn1);
            float e3 = __expf(sacc[nj][3] - mn1);
            ps0 += e0 + e1; ps1 += e2 + e3;
            int c0i = nj * 8 + 2 * lr;
            *(half2*)(Ps + (wr0 + lq) * FPP + c0i) = __floats2half2_rn(e0, e1);
            *(half2*)(Ps + (wr0 + lq + 8) * FPP + c0i) = __floats2half2_rn(e2, e3);
        }
        ps0 += __shfl_xor_sync(0xffffffffu, ps0, 1);
        ps0 += __shfl_xor_sync(0xffffffffu, ps0, 2);
        ps1 += __shfl_xor_sync(0xffffffffu, ps1, 1);
        ps1 += __shfl_xor_sync(0xffffffffu, ps1, 2);
        l0 = l0 * al0 + ps0;
        l1 = l1 * al1 + ps1;
        m0 = mn0; m1 = mn1;

        #pragma unroll
        for (int nj = 0; nj < 8; nj++) {
            oacc[nj][0] *= al0; oacc[nj][1] *= al0;
            oacc[nj][2] *= al1; oacc[nj][3] *= al1;
        }
        __syncwarp();

        #pragma unroll
        for (int kt = 0; kt < 8; kt++) {
            uint32_t a0, a1, a2, a3;
            LDSM_X4(a0, a1, a2, a3,
                    smw + (uint32_t)(FPO + (wr0 + rsel) * FPP + kt * 16 + ksel) * 2);
            #pragma unroll
            for (int njp = 0; njp < 4; njp++) {
                uint32_t b0, b1, b2, b3;
                LDSM_X4_T(b0, b1, b2, b3,
                          smw + (uint32_t)(FVO + (kt * 16 + rsel) * FQP + njp * 16 + ksel) * 2);
                mma_f16(oacc[2 * njp],     a0, a1, a2, a3, b0, b1);
                mma_f16(oacc[2 * njp + 1], a0, a1, a2, a3, b2, b3);
            }
        }
        __syncthreads();
    }

    float il0 = 1.0f / l0, il1 = 1.0f / l1;
    int r0 = b * 1024 + qb * 128 + wr0 + lq;
    #pragma unroll
    for (int nj = 0; nj < 8; nj++) {
        int cg = h * HD + nj * 8 + 2 * lr;
        *(half2*)(attn + (size_t)r0 * DD + cg) =
            __floats2half2_rn(oacc[nj][0] * il0, oacc[nj][1] * il0);
        *(half2*)(attn + (size_t)(r0 + 8) * DD + cg) =
            __floats2half2_rn(oacc[nj][2] * il1, oacc[nj][3] * il1);
    }
}

// ================= small kernels (unchanged R12) =================
__global__ void __launch_bounds__(256) mod2_k(const float* __restrict__ t_cond,
                                              const float* __restrict__ adaW,
                                              const float* __restrict__ adab,
                                              float* __restrict__ mod,
                                              const int* __restrict__ en32) {
    if (blockIdx.x == 96) {
        __shared__ int shd[8];
        int f = 0;
        #pragma unroll
        for (int j = 0; j < 4; j++) {
            int v = en32[threadIdx.x * 4 + j];
            f |= (v & ~1) ? 1 : 0;
        }
        #pragma unroll
        for (int o = 16; o; o >>= 1) f |= __shfl_xor_sync(0xffffffffu, f, o);
        if ((threadIdx.x & 31) == 0) shd[threadIdx.x >> 5] = f;
        __syncthreads();
        if (threadIdx.x == 0) {
            int t = 0;
            #pragma unroll
            for (int i = 0; i < 8; i++) t |= shd[i];
            g_enIsByte = t;
        }
        return;
    }
    __shared__ float tc[4][1024];
    __shared__ float part[4][4][64];
    for (int i = threadIdx.x; i < 4096; i += 256)
        tc[i >> 10][i & 1023] = t_cond[i];
    __syncthreads();
    const int cc = blockIdx.x * 64;
    const int c = threadIdx.x & 63, kq = threadIdx.x >> 6;
    float a0 = 0.f, a1 = 0.f, a2 = 0.f, a3 = 0.f;
    const int kb = kq * 256;
    #pragma unroll 4
    for (int k = kb; k < kb + 256; k++) {
        float w = adaW[(size_t)k * SIXD + cc + c];
        a0 = fmaf(tc[0][k], w, a0);
        a1 = fmaf(tc[1][k], w, a1);
        a2 = fmaf(tc[2][k], w, a2);
        a3 = fmaf(tc[3][k], w, a3);
    }
    part[kq][0][c] = a0; part[kq][1][c] = a1;
    part[kq][2][c] = a2; part[kq][3][c] = a3;
    __syncthreads();
    if (kq < 4 && threadIdx.x < 64) {
        #pragma unroll
        for (int b = 0; b < 4; b++) {
            float s = part[0][b][c] + part[1][b][c] + part[2][b][c] + part[3][b][c];
            mod[b * SIXD + cc + c] = s + adab[cc + c];
        }
    }
}

__global__ void __launch_bounds__(256) wcvt_all_k(
    const float* __restrict__ s0, __half* __restrict__ d0,
    const float* __restrict__ s1, __half* __restrict__ d1,
    const float* __restrict__ s2, __half* __restrict__ d2,
    const float* __restrict__ s3, __half* __restrict__ d3,
    const float* __restrict__ s4, __half* __restrict__ d4)
{
    int bx = blockIdx.x;
    const float* src; __half* dst; int off;
    if (bx < 256)       { src = s0; dst = d0; off = bx; }
    else if (bx < 768)  { src = s1; dst = d1; off = bx - 256; }
    else if (bx < 1024) { src = s2; dst = d2; off = bx - 768; }
    else if (bx < 2048) { src = s3; dst = d3; off = bx - 1024; }
    else                { src = s4; dst = d4; off = bx - 2048; }
    size_t base = ((size_t)off * 256 + threadIdx.x) * 16;
    #pragma unroll
    for (int j = 0; j < 4; j++) {
        float4 v = *(const float4*)(src + base + 4 * j);
        half2* d = (half2*)(dst + base + 4 * j);
        d[0] = __floats2half2_rn(v.x, v.y);
        d[1] = __floats2half2_rn(v.z, v.w);
    }
}

__device__ __forceinline__ void ln_row_body(const float* __restrict__ xr,
                                            const float* __restrict__ w,
                                            const float* __restrict__ mod,
                                            int b, int shOff, int scOff, int useMod,
                                            __half* __restrict__ orow, float* sh) {
    int tid = threadIdx.x;
    float v[4];
    float s = 0.f, s2 = 0.f;
    #pragma unroll
    for (int j = 0; j < 4; j++) {
        v[j] = xr[tid + j * 256];
        s += v[j];
        s2 = fmaf(v[j], v[j], s2);
    }
    #pragma unroll
    for (int o = 16; o; o >>= 1) {
        s  += __shfl_xor_sync(0xffffffffu, s, o);
        s2 += __shfl_xor_sync(0xffffffffu, s2, o);
    }
    if ((tid & 31) == 0) { sh[tid >> 5] = s; sh[8 + (tid >> 5)] = s2; }
    __syncthreads();
    if (tid == 0) {
        float t = 0.f, t2 = 0.f;
        #pragma unroll
        for (int i = 0; i < 8; i++) { t += sh[i]; t2 += sh[8 + i]; }
        sh[16] = t; sh[17] = t2;
    }
    __syncthreads();
    float mu = sh[16] * (1.0f / DD);
    float var = sh[17] * (1.0f / DD) - mu * mu;
    float rs = rsqrtf(var + 1e-5f);
    #pragma unroll
    for (int j = 0; j < 4; j++) {
        int d = tid + j * 256;
        float y = (v[j] - mu) * rs * w[d];
        if (useMod) y = y * (1.0f + mod[b * SIXD + scOff + d]) + mod[b * SIXD + shOff + d];
        orow[d] = __float2half_rn(y);
    }
}

__global__ void __launch_bounds__(256) ln_pair_k(const float* __restrict__ xq,
                                                 const float* __restrict__ xkv,
                                                 const float* __restrict__ wq,
                                                 const float* __restrict__ wkv,
                                                 const float* __restrict__ mod,
                                                 __half* __restrict__ oq,
                                                 __half* __restrict__ okv) {
    __shared__ float sh[18];
    int half = blockIdx.x >> 12;
    int row = blockIdx.x & 4095;
    int b = row >> 10;
    if (half == 0)
        ln_row_body(xq + (size_t)row * DD, wq, mod, b, 0, DD, 1, oq + (size_t)row * DD, sh);
    else
        ln_row_body(xkv + (size_t)row * DD, wkv, mod, b, 0, 0, 0, okv + (size_t)row * DD, sh);
}

__global__ void __launch_bounds__(256) ln_one_k(const float* __restrict__ x,
                                                const float* __restrict__ w,
                                                const float* __restrict__ mod,
                                                int shOff, int scOff,
                                                __half* __restrict__ out) {
    __shared__ float sh[18];
    int row = blockIdx.x;
    int b = row >> 10;
    ln_row_body(x + (size_t)row * DD, w, mod, b, shOff, scOff, 1, out + (size_t)row * DD, sh);
}

// ================= host =================
extern "C" void kernel_launch(void* const* d_in, const int* in_sizes, int n_in,
                              void* d_out, int out_size) {
    const float* q_x    = (const float*)d_in[0];
    const float* kv_x   = (const float*)d_in[1];
    const float* t_cond = (const float*)d_in[2];
    const float* cos_q  = (const float*)d_in[3];
    const float* sin_q  = (const float*)d_in[4];
    const float* cos_k  = (const float*)d_in[5];
    const float* sin_k  = (const float*)d_in[6];
    const int*   grp    = (const int*)d_in[7];
    const void*  en     = d_in[8];
    const float* qn_w   = (const float*)d_in[9];
    const float* kvn_w  = (const float*)d_in[10];
    const float* n2_w   = (const float*)d_in[11];
    const float* Wq     = (const float*)d_in[12];
    const float* Wkv    = (const float*)d_in[13];
    const float* Wo     = (const float*)d_in[14];
    const float* W1     = (const float*)d_in[15];
    const float* b1     = (const float*)d_in[16];
    const float* W2     = (const float*)d_in[17];
    const float* b2     = (const float*)d_in[18];
    const float* adaW   = (const float*)d_in[19];
    const float* adab   = (const float*)d_in[20];
    float* out = (float*)d_out;

    float *mod, *x;
    __half *qn_h, *kvn_h, *q_h, *kv_h, *attn_h, *hh, *h1_h;
    __half *wq_h, *wkv_h, *wo_h, *w1_h, *w2_h;
    cudaGetSymbolAddress((void**)&mod,    g_mod);
    cudaGetSymbolAddress((void**)&x,      g_x);
    cudaGetSymbolAddress((void**)&qn_h,   g_qn_h);
    cudaGetSymbolAddress((void**)&kvn_h,  g_kvn_h);
    cudaGetSymbolAddress((void**)&q_h,    g_q_h);
    cudaGetSymbolAddress((void**)&kv_h,   g_kv_h);
    cudaGetSymbolAddress((void**)&attn_h, g_attn_h);
    cudaGetSymbolAddress((void**)&hh,     g_hh);
    cudaGetSymbolAddress((void**)&h1_h,   g_h1_h);
    cudaGetSymbolAddress((void**)&wq_h,   g_wq_h);
    cudaGetSymbolAddress((void**)&wkv_h,  g_wkv_h);
    cudaGetSymbolAddress((void**)&wo_h,   g_wo_h);
    cudaGetSymbolAddress((void**)&w1_h,   g_w1_h);
    cudaGetSymbolAddress((void**)&w2_h,   g_w2_h);

    cudaFuncSetAttribute(gemm_h<0>, cudaFuncAttributeMaxDynamicSharedMemorySize, GSM_BYTES);
    cudaFuncSetAttribute(gemm_h<1>, cudaFuncAttributeMaxDynamicSharedMemorySize, GSM_BYTES);
    cudaFuncSetAttribute(gemm_h<2>, cudaFuncAttributeMaxDynamicSharedMemorySize, GSM_BYTES);
    cudaFuncSetAttribute(flash_h, cudaFuncAttributeMaxDynamicSharedMemorySize, FL_BYTES);

    static cudaStream_t s1 = nullptr;
    static cudaEvent_t eva = nullptr, evb = nullptr, evc = nullptr, evd = nullptr;
    static int sinit = 0;
    if (sinit == 0) {
        if (cudaStreamCreateWithFlags(&s1, cudaStreamNonBlocking) == cudaSuccess &&
            cudaEventCreateWithFlags(&eva, cudaEventDisableTiming) == cudaSuccess &&
            cudaEventCreateWithFlags(&evb, cudaEventDisableTiming) == cudaSuccess &&
            cudaEventCreateWithFlags(&evc, cudaEventDisableTiming) == cudaSuccess &&
            cudaEventCreateWithFlags(&evd, cudaEventDisableTiming) == cudaSuccess)
            sinit = 1;
        else
            sinit = -1;
    }
    const bool useStreams = (sinit == 1);

    if (useStreams) {
        cudaEventRecord(eva, 0);
        cudaStreamWaitEvent(s1, eva, 0);
        wcvt_all_k<<<3072, 256, 0, s1>>>(Wq, wq_h, Wkv, wkv_h, Wo, wo_h, W1, w1_h, W2, w2_h);
        cudaEventRecord(evb, s1);
    } else {
        wcvt_all_k<<<3072, 256>>>(Wq, wq_h, Wkv, wkv_h, Wo, wo_h, W1, w1_h, W2, w2_h);
    }

    mod2_k<<<97, 256>>>(t_cond, adaW, adab, mod, (const int*)en);
    ln_pair_k<<<8192, 256>>>(q_x, kv_x, qn_w, kvn_w, mod, qn_h, kvn_h);

    if (useStreams) {
        cudaStreamWaitEvent(0, evb, 0);
        cudaEventRecord(evc, 0);
        cudaStreamWaitEvent(s1, evc, 0);
        gemm_h<0><<<dim3(8, 32), 256, GSM_BYTES, s1>>>(
            qn_h, wq_h, q_h, DD, DD, DD, DD, nullptr, nullptr, 0, nullptr, nullptr);
        cudaEventRecord(evd, s1);
        gemm_h<0><<<dim3(16, 32), 256, GSM_BYTES>>>(
            kvn_h, wkv_h, kv_h, DD, DD, 2 * DD, 2 * DD, nullptr, nullptr, 0, nullptr, nullptr);
        cudaStreamWaitEvent(0, evd, 0);
    } else {
        gemm_h<0><<<dim3(8, 32), 256, GSM_BYTES>>>(
            qn_h, wq_h, q_h, DD, DD, DD, DD, nullptr, nullptr, 0, nullptr, nullptr);
        gemm_h<0><<<dim3(16, 32), 256, GSM_BYTES>>>(
            kvn_h, wkv_h, kv_h, DD, DD, 2 * DD, 2 * DD, nullptr, nullptr, 0, nullptr, nullptr);
    }

    flash_h<<<dim3(SS / 128, BB * HH), 256, FL_BYTES>>>(
        q_h, kv_h, grp, attn_h, cos_q, sin_q, cos_k, sin_k);

    gemm_h<2><<<dim3(8, 32), 256, GSM_BYTES>>>(
        attn_h, wo_h, x, DD, DD, DD, DD, nullptr, mod, 2 * DD, en, q_x);

    ln_one_k<<<NBS, 256>>>(x, n2_w, mod, 3 * DD, 4 * DD, hh);

    gemm_h<1><<<dim3(32, 32), 256, GSM_BYTES>>>(
        hh, w1_h, h1_h, DD, DD, MRD, MRD, b1, nullptr, 0, nullptr, nullptr);
    gemm_h<2><<<dim3(8, 32), 256, GSM_BYTES>>>(
        h1_h, w2_h, out, MRD, MRD, DD, DD, b2, mod, 5 * DD, en, x);
}

// round 16
// speedup vs baseline: 1.1572x; 1.1572x over previous
#include <cuda_runtime.h>
#include <cuda_fp16.h>
#include <cstdint>

// Problem constants
#define BB 4
#define SS 1024
#define KK 1024
#define DD 1024
#define HH 16
#define HD 64
#define MRD 4096
#define SIXD 6144
#define NBS 4096
#define INV_SQRT_HD 0.125f
#define GELU_C 0.7978845608028654f

// ---------------- scratch ----------------
__device__ __align__(16) float  g_mod[BB * SIXD];
__device__ __align__(16) float  g_x[NBS * DD];
__device__ __align__(16) __half g_qn_h[NBS * DD];
__device__ __align__(16) __half g_kvn_h[NBS * DD];
__device__ __align__(16) __half g_q_h[NBS * DD];
__device__ __align__(16) __half g_kv_h[NBS * 2 * DD];
__device__ __align__(16) __half g_attn_h[NBS * DD];
__device__ __align__(16) __half g_hh[NBS * DD];
__device__ __align__(16) __half g_h1_h[(size_t)NBS * MRD];
__device__ __align__(16) __half g_wq_h[DD * DD];
__device__ __align__(16) __half g_wkv_h[DD * 2 * DD];
__device__ __align__(16) __half g_wo_h[DD * DD];
__device__ __align__(16) __half g_w1_h[DD * MRD];
__device__ __align__(16) __half g_w2_h[MRD * DD];
__device__ int    g_enIsByte;

// ================= PTX helpers =================
__device__ __forceinline__ uint32_t smem_u32(const void* p) {
    uint32_t a;
    asm("{ .reg .u64 t; cvta.to.shared.u64 t, %1; cvt.u32.u64 %0, t; }" : "=r"(a) : "l"(p));
    return a;
}
#define CP_ASYNC16(sa, ga) \
    asm volatile("cp.async.ca.shared.global [%0], [%1], 16;" :: "r"(sa), "l"(ga) : "memory")
#define CP_COMMIT() asm volatile("cp.async.commit_group;" ::: "memory")
#define CP_WAIT0()  asm volatile("cp.async.wait_group 0;" ::: "memory")
#define CP_WAIT1()  asm volatile("cp.async.wait_group 1;" ::: "memory")

#define LDSM_X4(d0, d1, d2, d3, addr)                                          \
    asm volatile("ldmatrix.sync.aligned.m8n8.x4.shared.b16 {%0,%1,%2,%3}, [%4];" \
        : "=r"(d0), "=r"(d1), "=r"(d2), "=r"(d3) : "r"(addr))
#define LDSM_X4_T(d0, d1, d2, d3, addr)                                        \
    asm volatile("ldmatrix.sync.aligned.m8n8.x4.trans.shared.b16 {%0,%1,%2,%3}, [%4];" \
        : "=r"(d0), "=r"(d1), "=r"(d2), "=r"(d3) : "r"(addr))

__device__ __forceinline__ void mma_f16(float* c, uint32_t a0, uint32_t a1,
                                        uint32_t a2, uint32_t a3,
                                        uint32_t b0, uint32_t b1) {
    asm volatile(
        "mma.sync.aligned.m16n8k16.row.col.f32.f16.f16.f32 "
        "{%0,%1,%2,%3}, {%4,%5,%6,%7}, {%8,%9}, {%0,%1,%2,%3};"
        : "+f"(c[0]), "+f"(c[1]), "+f"(c[2]), "+f"(c[3])
        : "r"(a0), "r"(a1), "r"(a2), "r"(a3), "r"(b0), "r"(b1));
}
__device__ __forceinline__ float gelu_f(float v) {
    float u = GELU_C * (v + 0.044715f * v * v * v);
    u = fminf(fmaxf(u, -15.f), 15.f);
    float t = __expf(2.0f * u);
    return 0.5f * v * (1.0f + (t - 1.0f) / (t + 1.0f));
}

// ================= fp16 mma GEMM: BK=64, 2-stage, occ-2 (exact R12) =================
#define KPA 72
#define BPB 136
#define ASTG (128 * KPA)
#define BSTG (64 * BPB)
#define GSM_BYTES (2 * (ASTG + BSTG) * 2)   // 71680 bytes

template <int EPI>
__global__ void __launch_bounds__(256, 2) gemm_h(
    const __half* __restrict__ A, const __half* __restrict__ B, void* __restrict__ Cv,
    int Kd, int lda, int ldb, int ldc,
    const float* __restrict__ bias, const float* __restrict__ modv, int goff,
    const void* __restrict__ en, const float* __restrict__ basep)
{
    extern __shared__ __half smh[];
    const uint32_t smw = smem_u32(smh);

    const int tid = threadIdx.x;
    const int lane = tid & 31;
    const int wid = tid >> 5;
    const int wm = wid >> 2, wn = wid & 3;
    const int lq = lane >> 2, lr = lane & 3;
    const int rsel = lane & 15;
    const int ksel = (lane >> 4) * 8;

    const int row0 = blockIdx.y * 128, col0 = blockIdx.x * 128;

    float acc[4][4][4];
    #pragma unroll
    for (int i = 0; i < 4; i++)
        #pragma unroll
        for (int j = 0; j < 4; j++)
            #pragma unroll
            for (int e = 0; e < 4; e++) acc[i][j][e] = 0.f;

    const int nk = Kd / 64;

    auto load_stage = [&](int ks) {
        const int k0 = ks * 64;
        const int s = ks & 1;
        uint32_t abase = smw + (uint32_t)s * ASTG * 2;
        #pragma unroll
        for (int j = 0; j < 4; j++) {
            int idx = tid + 256 * j;
            int r = idx >> 3, c = idx & 7;
            CP_ASYNC16(abase + (uint32_t)(r * KPA + c * 8) * 2,
                       A + (size_t)(row0 + r) * lda + k0 + c * 8);
        }
        uint32_t bbase = smw + (uint32_t)(2 * ASTG + s * BSTG) * 2;
        #pragma unroll
        for (int j = 0; j < 4; j++) {
            int idx = tid + 256 * j;
            int r = idx >> 4, c = idx & 15;
            CP_ASYNC16(bbase + (uint32_t)(r * BPB + c * 8) * 2,
                       B + (size_t)(k0 + r) * ldb + col0 + c * 8);
        }
        CP_COMMIT();
    };

    load_stage(0);
    if (nk > 1) load_stage(1);

    for (int i = 0; i < nk; i++) {
        if (i == nk - 1) CP_WAIT0(); else CP_WAIT1();
        __syncthreads();

        const int s = i & 1;
        const uint32_t abase = smw + (uint32_t)s * ASTG * 2;
        const uint32_t bbase = smw + (uint32_t)(2 * ASTG + s * BSTG) * 2;

        #pragma unroll
        for (int kt = 0; kt < 4; kt++) {
            uint32_t af[4][4];
            #pragma unroll
            for (int mi = 0; mi < 4; mi++) {
                int rm = wm * 64 + mi * 16;
                LDSM_X4(af[mi][0], af[mi][1], af[mi][2], af[mi][3],
                        abase + (uint32_t)((rm + rsel) * KPA + kt * 16 + ksel) * 2);
            }
            #pragma unroll
            for (int njp = 0; njp < 2; njp++) {
                uint32_t b0, b1, b2, b3;
                int n0 = wn * 32 + njp * 16;
                LDSM_X4_T(b0, b1, b2, b3,
                          bbase + (uint32_t)((kt * 16 + rsel) * BPB + n0 + ksel) * 2);
                #pragma unroll
                for (int mi = 0; mi < 4; mi++) {
                    mma_f16(acc[mi][2 * njp],     af[mi][0], af[mi][1], af[mi][2], af[mi][3], b0, b1);
                    mma_f16(acc[mi][2 * njp + 1], af[mi][0], af[mi][1], af[mi][2], af[mi][3], b2, b3);
                }
            }
        }
        __syncthreads();
        if (i + 2 < nk) load_stage(i + 2);
    }

    #pragma unroll
    for (int mi = 0; mi < 4; mi++) {
        int rg = row0 + wm * 64 + mi * 16 + lq;
        float g0 = 0.f, g1 = 0.f;
        if (EPI == 2) {
            int e0 = g_enIsByte ? (int)((const unsigned char*)en)[rg] : ((const int*)en)[rg];
            int e1 = g_enIsByte ? (int)((const unsigned char*)en)[rg + 8] : ((const int*)en)[rg + 8];
            g0 = e0 ? 1.f : 0.f;
            g1 = e1 ? 1.f : 0.f;
        }
        #pragma unroll
        for (int nj = 0; nj < 4; nj++) {
            int cg = col0 + wn * 32 + nj * 8 + lr * 2;
            float v0 = acc[mi][nj][0], v1 = acc[mi][nj][1];
            float v2 = acc[mi][nj][2], v3 = acc[mi][nj][3];
            if (EPI == 0) {
                __half* C = (__half*)Cv;
                *(half2*)(C + (size_t)rg * ldc + cg) = __floats2half2_rn(v0, v1);
                *(half2*)(C + (size_t)(rg + 8) * ldc + cg) = __floats2half2_rn(v2, v3);
            } else if (EPI == 1) {
                float b0 = bias[cg], b1v = bias[cg + 1];
                __half* C = (__half*)Cv;
                *(half2*)(C + (size_t)rg * ldc + cg) =
                    __floats2half2_rn(gelu_f(v0 + b0), gelu_f(v1 + b1v));
                *(half2*)(C + (size_t)(rg + 8) * ldc + cg) =
                    __floats2half2_rn(gelu_f(v2 + b0), gelu_f(v3 + b1v));
            } else {
                float b0 = bias ? bias[cg] : 0.f, b1v = bias ? bias[cg + 1] : 0.f;
                int bb0 = rg >> 10, bb1 = (rg + 8) >> 10;
                float m00 = modv[bb0 * SIXD + goff + cg];
                float m01 = modv[bb0 * SIXD + goff + cg + 1];
                float m10 = modv[bb1 * SIXD + goff + cg];
                float m11 = modv[bb1 * SIXD + goff + cg + 1];
                float* C = (float*)Cv;
                *(float2*)(C + (size_t)rg * ldc + cg) = make_float2(
                    basep[(size_t)rg * DD + cg] + g0 * m00 * (v0 + b0),
                    basep[(size_t)rg * DD + cg + 1] + g0 * m01 * (v1 + b1v));
                *(float2*)(C + (size_t)(rg + 8) * ldc + cg) = make_float2(
                    basep[(size_t)(rg + 8) * DD + cg] + g1 * m10 * (v2 + b0),
                    basep[(size_t)(rg + 8) * DD + cg + 1] + g1 * m11 * (v3 + b1v));
            }
        }
    }
}

// ================= flash attention (fp16 mma, fused RoPE, occ-2) =================
// grpq: half-offsets [45056, 45312) (128 ints). grpkAll: [45312, 47360) (1024 ints).
#define FQP 72
#define FPP 136
#define FKO 9216
#define FVO 18432
#define FPO 27648
#define FL_GRPQ 45056
#define FL_GRPK 45312
#define FL_BYTES (FL_GRPK * 2 + 4096)   // 94720

__global__ void __launch_bounds__(256, 2) flash_h(
    const __half* __restrict__ q, const __half* __restrict__ kv,
    const int* __restrict__ grp, __half* __restrict__ attn,
    const float* __restrict__ cosq, const float* __restrict__ sinq,
    const float* __restrict__ cosk, const float* __restrict__ sink)
{
    extern __shared__ __half smh[];
    const uint32_t smw = smem_u32(smh);
    int* grpq = (int*)(smh + FL_GRPQ);
    int* grpkAll = (int*)(smh + FL_GRPK);

    const int tid = threadIdx.x;
    const int lane = tid & 31;
    const int wid = tid >> 5;
    const int wr0 = wid * 16;
    const int lq = lane >> 2, lr = lane & 3;
    const int rsel = lane & 15;
    const int ksel = (lane >> 4) * 8;
    const int nsel = (lane & 7) + (lane >> 4) * 8;
    const int kse2 = ((lane >> 3) & 1) * 8;

    const int qb = blockIdx.x;
    const int b = blockIdx.y >> 4;
    const int h = blockIdx.y & 15;

    // ---- load Q tile with fused RoPE + all group ids ----
    #pragma unroll
    for (int j = 0; j < 4; j++) {
        int idx = tid + 256 * j;
        int r = idx >> 3, c8 = idx & 7;
        int s = qb * 128 + r;
        const __half* row = q + (size_t)(b * SS + s) * DD + h * HD;
        uint4 own = *(const uint4*)(row + 8 * c8);
        uint4 par = *(const uint4*)(row + 8 * (c8 ^ 4));
        const __half* oh = (const __half*)&own;
        const __half* ph = (const __half*)&par;
        float4 cz0 = *(const float4*)(cosq + s * HD + 8 * c8);
        float4 cz1 = *(const float4*)(cosq + s * HD + 8 * c8 + 4);
        float4 sz0 = *(const float4*)(sinq + s * HD + 8 * c8);
        float4 sz1 = *(const float4*)(sinq + s * HD + 8 * c8 + 4);
        float czv[8] = {cz0.x, cz0.y, cz0.z, cz0.w, cz1.x, cz1.y, cz1.z, cz1.w};
        float szv[8] = {sz0.x, sz0.y, sz0.z, sz0.w, sz1.x, sz1.y, sz1.z, sz1.w};
        float sgn = (c8 & 4) ? 1.f : -1.f;
        __half res[8];
        #pragma unroll
        for (int e = 0; e < 8; e++) {
            float x1 = __half2float(oh[e]);
            float x2 = __half2float(ph[e]);
            res[e] = __float2half_rn(x1 * czv[e] + sgn * x2 * szv[e]);
        }
        *(uint4*)(smh + r * FQP + 8 * c8) = *(uint4*)res;
    }
    if (tid < 128) grpq[tid] = grp[b * 1024 + qb * 128 + tid];
    #pragma unroll
    for (int j = 0; j < 4; j++)
        grpkAll[tid + 256 * j] = grp[b * 1024 + tid + 256 * j];

    float m0 = -3.0e38f, m1 = -3.0e38f, l0 = 0.f, l1 = 0.f;
    float oacc[8][4];
    #pragma unroll
    for (int j = 0; j < 8; j++)
        #pragma unroll
        for (int e = 0; e < 4; e++) oacc[j][e] = 0.f;

    for (int kc = 0; kc < 8; kc++) {
        const int* grpk = grpkAll + kc * 128;
        // ---- V chunk via cp.async ----
        #pragma unroll
        for (int j = 0; j < 4; j++) {
            int idx = tid + 256 * j;
            int r = idx >> 3, c = idx & 7;
            CP_ASYNC16(smw + (uint32_t)(FVO + r * FQP + c * 8) * 2,
                       kv + (size_t)(b * 1024 + kc * 128 + r) * (2 * DD) + DD + h * HD + c * 8);
        }
        CP_COMMIT();
        // ---- K chunk with fused RoPE ----
        #pragma unroll
        for (int j = 0; j < 4; j++) {
            int idx = tid + 256 * j;
            int r = idx >> 3, c8 = idx & 7;
            int s = kc * 128 + r;
            const __half* row = kv + (size_t)(b * 1024 + s) * (2 * DD) + h * HD;
            uint4 own = *(const uint4*)(row + 8 * c8);
            uint4 par = *(const uint4*)(row + 8 * (c8 ^ 4));
            const __half* oh = (const __half*)&own;
            const __half* ph = (const __half*)&par;
            float4 cz0 = *(const float4*)(cosk + s * HD + 8 * c8);
            float4 cz1 = *(const float4*)(cosk + s * HD + 8 * c8 + 4);
            float4 sz0 = *(const float4*)(sink + s * HD + 8 * c8);
            float4 sz1 = *(const float4*)(sink + s * HD + 8 * c8 + 4);
            float czv[8] = {cz0.x, cz0.y, cz0.z, cz0.w, cz1.x, cz1.y, cz1.z, cz1.w};
            float szv[8] = {sz0.x, sz0.y, sz0.z, sz0.w, sz1.x, sz1.y, sz1.z, sz1.w};
            float sgn = (c8 & 4) ? 1.f : -1.f;
            __half res[8];
            #pragma unroll
            for (int e = 0; e < 8; e++) {
                float x1 = __half2float(oh[e]);
                float x2 = __half2float(ph[e]);
                res[e] = __float2half_rn(x1 * czv[e] + sgn * x2 * szv[e]);
            }
            *(uint4*)(smh + FKO + r * FQP + 8 * c8) = *(uint4*)res;
        }
        CP_WAIT0();
        __syncthreads();

        float sacc[16][4];
        #pragma unroll
        for (int nj = 0; nj < 16; nj++)
            #pragma unroll
            for (int e = 0; e < 4; e++) sacc[nj][e] = 0.f;

        #pragma unroll
        for (int kt = 0; kt < 4; kt++) {
            uint32_t a0, a1, a2, a3;
            LDSM_X4(a0, a1, a2, a3,
                    smw + (uint32_t)((wr0 + rsel) * FQP + kt * 16 + ksel) * 2);
            #pragma unroll
            for (int njp = 0; njp < 8; njp++) {
                uint32_t b0, b1, b2, b3;
                LDSM_X4(b0, b1, b2, b3,
                        smw + (uint32_t)(FKO + (njp * 16 + nsel) * FQP + kt * 16 + kse2) * 2);
                mma_f16(sacc[2 * njp],     a0, a1, a2, a3, b0, b1);
                mma_f16(sacc[2 * njp + 1], a0, a1, a2, a3, b2, b3);
            }
        }

        int gq0 = grpq[wr0 + lq], gq1 = grpq[wr0 + lq + 8];
        float rm0 = -3.0e38f, rm1 = -3.0e38f;
        #pragma unroll
        for (int nj = 0; nj < 16; nj++) {
            int c0i = nj * 8 + 2 * lr;
            int gk0 = grpk[c0i], gk1 = grpk[c0i + 1];
            float s0 = (gk0 != gq0) ? sacc[nj][0] * INV_SQRT_HD : -1.0e9f;
            float s1 = (gk1 != gq0) ? sacc[nj][1] * INV_SQRT_HD : -1.0e9f;
            float s2 = (gk0 != gq1) ? sacc[nj][2] * INV_SQRT_HD : -1.0e9f;
            float s3 = (gk1 != gq1) ? sacc[nj][3] * INV_SQRT_HD : -1.0e9f;
            sacc[nj][0] = s0; sacc[nj][1] = s1; sacc[nj][2] = s2; sacc[nj][3] = s3;
            rm0 = fmaxf(rm0, fmaxf(s0, s1));
            rm1 = fmaxf(rm1, fmaxf(s2, s3));
        }
        rm0 = fmaxf(rm0, __shfl_xor_sync(0xffffffffu, rm0, 1));
        rm0 = fmaxf(rm0, __shfl_xor_sync(0xffffffffu, rm0, 2));
        rm1 = fmaxf(rm1, __shfl_xor_sync(0xffffffffu, rm1, 1));
        rm1 = fmaxf(rm1, __shfl_xor_sync(0xffffffffu, rm1, 2));
        float mn0 = fmaxf(m0, rm0), mn1 = fmaxf(m1, rm1);
        float al0 = __expf(m0 - mn0), al1 = __expf(m1 - mn1);

        __half* Ps = smh + FPO;
        float ps0 = 0.f, ps1 = 0.f;
        #pragma unroll
        for (int nj = 0; nj < 16; nj++) {
            float e0 = __expf(sacc[nj][0] - mn0);
            float e1 = __expf(sacc[nj][1] - mn0);
            float e2 = __expf(sacc[nj][2] - mn1);
            float e3 = __expf(sacc[nj][3] - mn1);
            ps0 += e0 + e1; ps1 += e2 + e3;
            int c0i = nj * 8 + 2 * lr;
            *(half2*)(Ps + (wr0 + lq) * FPP + c0i) = __floats2half2_rn(e0, e1);
            *(half2*)(Ps + (wr0 + lq + 8) * FPP + c0i) = __floats2half2_rn(e2, e3);
        }
        ps0 += __shfl_xor_sync(0xffffffffu, ps0, 1);
        ps0 += __shfl_xor_sync(0xffffffffu, ps0, 2);
        ps1 += __shfl_xor_sync(0xffffffffu, ps1, 1);
        ps1 += __shfl_xor_sync(0xffffffffu, ps1, 2);
        l0 = l0 * al0 + ps0;
        l1 = l1 * al1 + ps1;
        m0 = mn0; m1 = mn1;

        #pragma unroll
        for (int nj = 0; nj < 8; nj++) {
            oacc[nj][0] *= al0; oacc[nj][1] *= al0;
            oacc[nj][2] *= al1; oacc[nj][3] *= al1;
        }
        __syncwarp();

        #pragma unroll
        for (int kt = 0; kt < 8; kt++) {
            uint32_t a0, a1, a2, a3;
            LDSM_X4(a0, a1, a2, a3,
                    smw + (uint32_t)(FPO + (wr0 + rsel) * FPP + kt * 16 + ksel) * 2);
            #pragma unroll
            for (int njp = 0; njp < 4; njp++) {
                uint32_t b0, b1, b2, b3;
                LDSM_X4_T(b0, b1, b2, b3,
                          smw + (uint32_t)(FVO + (kt * 16 + rsel) * FQP + njp * 16 + ksel) * 2);
                mma_f16(oacc[2 * njp],     a0, a1, a2, a3, b0, b1);
                mma_f16(oacc[2 * njp + 1], a0, a1, a2, a3, b2, b3);
            }
        }
        __syncthreads();
    }

    float il0 = 1.0f / l0, il1 = 1.0f / l1;
    int r0 = b * 1024 + qb * 128 + wr0 + lq;
    #pragma unroll
    for (int nj = 0; nj < 8; nj++) {
        int cg = h * HD + nj * 8 + 2 * lr;
        *(half2*)(attn + (size_t)r0 * DD + cg) =
            __floats2half2_rn(oacc[nj][0] * il0, oacc[nj][1] * il0);
        *(half2*)(attn + (size_t)(r0 + 8) * DD + cg) =
            __floats2half2_rn(oacc[nj][2] * il1, oacc[nj][3] * il1);
    }
}

// ================= small kernels (unchanged R12) =================
__global__ void __launch_bounds__(256) mod2_k(const float* __restrict__ t_cond,
                                              const float* __restrict__ adaW,
                                              const float* __restrict__ adab,
                                              float* __restrict__ mod,
                                              const int* __restrict__ en32) {
    if (blockIdx.x == 96) {
        __shared__ int shd[8];
        int f = 0;
        #pragma unroll
        for (int j = 0; j < 4; j++) {
            int v = en32[threadIdx.x * 4 + j];
            f |= (v & ~1) ? 1 : 0;
        }
        #pragma unroll
        for (int o = 16; o; o >>= 1) f |= __shfl_xor_sync(0xffffffffu, f, o);
        if ((threadIdx.x & 31) == 0) shd[threadIdx.x >> 5] = f;
        __syncthreads();
        if (threadIdx.x == 0) {
            int t = 0;
            #pragma unroll
            for (int i = 0; i < 8; i++) t |= shd[i];
            g_enIsByte = t;
        }
        return;
    }
    __shared__ float tc[4][1024];
    __shared__ float part[4][4][64];
    for (int i = threadIdx.x; i < 4096; i += 256)
        tc[i >> 10][i & 1023] = t_cond[i];
    __syncthreads();
    const int cc = blockIdx.x * 64;
    const int c = threadIdx.x & 63, kq = threadIdx.x >> 6;
    float a0 = 0.f, a1 = 0.f, a2 = 0.f, a3 = 0.f;
    const int kb = kq * 256;
    #pragma unroll 4
    for (int k = kb; k < kb + 256; k++) {
        float w = adaW[(size_t)k * SIXD + cc + c];
        a0 = fmaf(tc[0][k], w, a0);
        a1 = fmaf(tc[1][k], w, a1);
        a2 = fmaf(tc[2][k], w, a2);
        a3 = fmaf(tc[3][k], w, a3);
    }
    part[kq][0][c] = a0; part[kq][1][c] = a1;
    part[kq][2][c] = a2; part[kq][3][c] = a3;
    __syncthreads();
    if (kq < 4 && threadIdx.x < 64) {
        #pragma unroll
        for (int b = 0; b < 4; b++) {
            float s = part[0][b][c] + part[1][b][c] + part[2][b][c] + part[3][b][c];
            mod[b * SIXD + cc + c] = s + adab[cc + c];
        }
    }
}

__global__ void __launch_bounds__(256) wcvt_all_k(
    const float* __restrict__ s0, __half* __restrict__ d0,
    const float* __restrict__ s1, __half* __restrict__ d1,
    const float* __restrict__ s2, __half* __restrict__ d2,
    const float* __restrict__ s3, __half* __restrict__ d3,
    const float* __restrict__ s4, __half* __restrict__ d4)
{
    int bx = blockIdx.x;
    const float* src; __half* dst; int off;
    if (bx < 256)       { src = s0; dst = d0; off = bx; }
    else if (bx < 768)  { src = s1; dst = d1; off = bx - 256; }
    else if (bx < 1024) { src = s2; dst = d2; off = bx - 768; }
    else if (bx < 2048) { src = s3; dst = d3; off = bx - 1024; }
    else                { src = s4; dst = d4; off = bx - 2048; }
    size_t base = ((size_t)off * 256 + threadIdx.x) * 16;
    #pragma unroll
    for (int j = 0; j < 4; j++) {
        float4 v = *(const float4*)(src + base + 4 * j);
        half2* d = (half2*)(dst + base + 4 * j);
        d[0] = __floats2half2_rn(v.x, v.y);
        d[1] = __floats2half2_rn(v.z, v.w);
    }
}

__device__ __forceinline__ void ln_row_body(const float* __restrict__ xr,
                                            const float* __restrict__ w,
                                            const float* __restrict__ mod,
                                            int b, int shOff, int scOff, int useMod,
                                            __half* __restrict__ orow, float* sh) {
    int tid = threadIdx.x;
    float v[4];
    float s = 0.f, s2 = 0.f;
    #pragma unroll
    for (int j = 0; j < 4; j++) {
        v[j] = xr[tid + j * 256];
        s += v[j];
        s2 = fmaf(v[j], v[j], s2);
    }
    #pragma unroll
    for (int o = 16; o; o >>= 1) {
        s  += __shfl_xor_sync(0xffffffffu, s, o);
        s2 += __shfl_xor_sync(0xffffffffu, s2, o);
    }
    if ((tid & 31) == 0) { sh[tid >> 5] = s; sh[8 + (tid >> 5)] = s2; }
    __syncthreads();
    if (tid == 0) {
        float t = 0.f, t2 = 0.f;
        #pragma unroll
        for (int i = 0; i < 8; i++) { t += sh[i]; t2 += sh[8 + i]; }
        sh[16] = t; sh[17] = t2;
    }
    __syncthreads();
    float mu = sh[16] * (1.0f / DD);
    float var = sh[17] * (1.0f / DD) - mu * mu;
    float rs = rsqrtf(var + 1e-5f);
    #pragma unroll
    for (int j = 0; j < 4; j++) {
        int d = tid + j * 256;
        float y = (v[j] - mu) * rs * w[d];
        if (useMod) y = y * (1.0f + mod[b * SIXD + scOff + d]) + mod[b * SIXD + shOff + d];
        orow[d] = __float2half_rn(y);
    }
}

__global__ void __launch_bounds__(256) ln_pair_k(const float* __restrict__ xq,
                                                 const float* __restrict__ xkv,
                                                 const float* __restrict__ wq,
                                                 const float* __restrict__ wkv,
                                                 const float* __restrict__ mod,
                                                 __half* __restrict__ oq,
                                                 __half* __restrict__ okv) {
    __shared__ float sh[18];
    int half = blockIdx.x >> 12;
    int row = blockIdx.x & 4095;
    int b = row >> 10;
    if (half == 0)
        ln_row_body(xq + (size_t)row * DD, wq, mod, b, 0, DD, 1, oq + (size_t)row * DD, sh);
    else
        ln_row_body(xkv + (size_t)row * DD, wkv, mod, b, 0, 0, 0, okv + (size_t)row * DD, sh);
}

__global__ void __launch_bounds__(256) ln_one_k(const float* __restrict__ x,
                                                const float* __restrict__ w,
                                                const float* __restrict__ mod,
                                                int shOff, int scOff,
                                                __half* __restrict__ out) {
    __shared__ float sh[18];
    int row = blockIdx.x;
    int b = row >> 10;
    ln_row_body(x + (size_t)row * DD, w, mod, b, shOff, scOff, 1, out + (size_t)row * DD, sh);
}

// ================= host =================
extern "C" void kernel_launch(void* const* d_in, const int* in_sizes, int n_in,
                              void* d_out, int out_size) {
    const float* q_x    = (const float*)d_in[0];
    const float* kv_x   = (const float*)d_in[1];
    const float* t_cond = (const float*)d_in[2];
    const float* cos_q  = (const float*)d_in[3];
    const float* sin_q  = (const float*)d_in[4];
    const float* cos_k  = (const float*)d_in[5];
    const float* sin_k  = (const float*)d_in[6];
    const int*   grp    = (const int*)d_in[7];
    const void*  en     = d_in[8];
    const float* qn_w   = (const float*)d_in[9];
    const float* kvn_w  = (const float*)d_in[10];
    const float* n2_w   = (const float*)d_in[11];
    const float* Wq     = (const float*)d_in[12];
    const float* Wkv    = (const float*)d_in[13];
    const float* Wo     = (const float*)d_in[14];
    const float* W1     = (const float*)d_in[15];
    const float* b1     = (const float*)d_in[16];
    const float* W2     = (const float*)d_in[17];
    const float* b2     = (const float*)d_in[18];
    const float* adaW   = (const float*)d_in[19];
    const float* adab   = (const float*)d_in[20];
    float* out = (float*)d_out;

    float *mod, *x;
    __half *qn_h, *kvn_h, *q_h, *kv_h, *attn_h, *hh, *h1_h;
    __half *wq_h, *wkv_h, *wo_h, *w1_h, *w2_h;
    cudaGetSymbolAddress((void**)&mod,    g_mod);
    cudaGetSymbolAddress((void**)&x,      g_x);
    cudaGetSymbolAddress((void**)&qn_h,   g_qn_h);
    cudaGetSymbolAddress((void**)&kvn_h,  g_kvn_h);
    cudaGetSymbolAddress((void**)&q_h,    g_q_h);
    cudaGetSymbolAddress((void**)&kv_h,   g_kv_h);
    cudaGetSymbolAddress((void**)&attn_h, g_attn_h);
    cudaGetSymbolAddress((void**)&hh,     g_hh);
    cudaGetSymbolAddress((void**)&h1_h,   g_h1_h);
    cudaGetSymbolAddress((void**)&wq_h,   g_wq_h);
    cudaGetSymbolAddress((void**)&wkv_h,  g_wkv_h);
    cudaGetSymbolAddress((void**)&wo_h,   g_wo_h);
    cudaGetSymbolAddress((void**)&w1_h,   g_w1_h);
    cudaGetSymbolAddress((void**)&w2_h,   g_w2_h);

    cudaFuncSetAttribute(gemm_h<0>, cudaFuncAttributeMaxDynamicSharedMemorySize, GSM_BYTES);
    cudaFuncSetAttribute(gemm_h<1>, cudaFuncAttributeMaxDynamicSharedMemorySize, GSM_BYTES);
    cudaFuncSetAttribute(gemm_h<2>, cudaFuncAttributeMaxDynamicSharedMemorySize, GSM_BYTES);
    cudaFuncSetAttribute(flash_h, cudaFuncAttributeMaxDynamicSharedMemorySize, FL_BYTES);

    static cudaStream_t s1 = nullptr;
    static cudaEvent_t eva = nullptr, evb = nullptr, evc = nullptr, evd = nullptr;
    static int sinit = 0;
    if (sinit == 0) {
        if (cudaStreamCreateWithFlags(&s1, cudaStreamNonBlocking) == cudaSuccess &&
            cudaEventCreateWithFlags(&eva, cudaEventDisableTiming) == cudaSuccess &&
            cudaEventCreateWithFlags(&evb, cudaEventDisableTiming) == cudaSuccess &&
            cudaEventCreateWithFlags(&evc, cudaEventDisableTiming) == cudaSuccess &&
            cudaEventCreateWithFlags(&evd, cudaEventDisableTiming) == cudaSuccess)
            sinit = 1;
        else
            sinit = -1;
    }
    const bool useStreams = (sinit == 1);

    if (useStreams) {
        cudaEventRecord(eva, 0);
        cudaStreamWaitEvent(s1, eva, 0);
        wcvt_all_k<<<3072, 256, 0, s1>>>(Wq, wq_h, Wkv, wkv_h, Wo, wo_h, W1, w1_h, W2, w2_h);
        cudaEventRecord(evb, s1);
    } else {
        wcvt_all_k<<<3072, 256>>>(Wq, wq_h, Wkv, wkv_h, Wo, wo_h, W1, w1_h, W2, w2_h);
    }

    mod2_k<<<97, 256>>>(t_cond, adaW, adab, mod, (const int*)en);
    ln_pair_k<<<8192, 256>>>(q_x, kv_x, qn_w, kvn_w, mod, qn_h, kvn_h);

    if (useStreams) {
        cudaStreamWaitEvent(0, evb, 0);
        cudaEventRecord(evc, 0);
        cudaStreamWaitEvent(s1, evc, 0);
        gemm_h<0><<<dim3(8, 32), 256, GSM_BYTES, s1>>>(
            qn_h, wq_h, q_h, DD, DD, DD, DD, nullptr, nullptr, 0, nullptr, nullptr);
        cudaEventRecord(evd, s1);
        gemm_h<0><<<dim3(16, 32), 256, GSM_BYTES>>>(
            kvn_h, wkv_h, kv_h, DD, DD, 2 * DD, 2 * DD, nullptr, nullptr, 0, nullptr, nullptr);
        cudaStreamWaitEvent(0, evd, 0);
    } else {
        gemm_h<0><<<dim3(8, 32), 256, GSM_BYTES>>>(
            qn_h, wq_h, q_h, DD, DD, DD, DD, nullptr, nullptr, 0, nullptr, nullptr);
        gemm_h<0><<<dim3(16, 32), 256, GSM_BYTES>>>(
            kvn_h, wkv_h, kv_h, DD, DD, 2 * DD, 2 * DD, nullptr, nullptr, 0, nullptr, nullptr);
    }

    flash_h<<<dim3(SS / 128, BB * HH), 256, FL_BYTES>>>(
        q_h, kv_h, grp, attn_h, cos_q, sin_q, cos_k, sin_k);

    gemm_h<2><<<dim3(8, 32), 256, GSM_BYTES>>>(
        attn_h, wo_h, x, DD, DD, DD, DD, nullptr, mod, 2 * DD, en, q_x);

    ln_one_k<<<NBS, 256>>>(x, n2_w, mod, 3 * DD, 4 * DD, hh);

    gemm_h<1><<<dim3(32, 32), 256, GSM_BYTES>>>(
        hh, w1_h, h1_h, DD, DD, MRD, MRD, b1, nullptr, 0, nullptr, nullptr);
    gemm_h<2><<<dim3(8, 32), 256, GSM_BYTES>>>(
        h1_h, w2_h, out, MRD, MRD, DD, DD, b2, mod, 5 * DD, en, x);
}

// round 17
// speedup vs baseline: 1.2563x; 1.0856x over previous
#include <cuda_runtime.h>
#include <cuda_fp16.h>
#include <cstdint>

// Problem constants
#define BB 4
#define SS 1024
#define KK 1024
#define DD 1024
#define HH 16
#define HD 64
#define MRD 4096
#define SIXD 6144
#define NBS 4096
#define INV_SQRT_HD 0.125f
#define GELU_C 0.7978845608028654f

// ---------------- scratch ----------------
__device__ __align__(16) float  g_mod[BB * SIXD];
__device__ __align__(16) float  g_x[NBS * DD];
__device__ __align__(16) __half g_qn_h[NBS * DD];
__device__ __align__(16) __half g_kvn_h[NBS * DD];
__device__ __align__(16) __half g_q_h[NBS * DD];
__device__ __align__(16) __half g_kv_h[NBS * 2 * DD];
__device__ __align__(16) __half g_attn_h[NBS * DD];
__device__ __align__(16) __half g_hh[NBS * DD];
__device__ __align__(16) __half g_h1_h[(size_t)NBS * MRD];
__device__ __align__(16) __half g_wq_h[DD * DD];
__device__ __align__(16) __half g_wkv_h[DD * 2 * DD];
__device__ __align__(16) __half g_wo_h[DD * DD];
__device__ __align__(16) __half g_w1_h[DD * MRD];
__device__ __align__(16) __half g_w2_h[MRD * DD];
__device__ int    g_enIsByte;

// ================= PTX helpers =================
__device__ __forceinline__ uint32_t smem_u32(const void* p) {
    uint32_t a;
    asm("{ .reg .u64 t; cvta.to.shared.u64 t, %1; cvt.u32.u64 %0, t; }" : "=r"(a) : "l"(p));
    return a;
}
#define CP_ASYNC16(sa, ga) \
    asm volatile("cp.async.ca.shared.global [%0], [%1], 16;" :: "r"(sa), "l"(ga) : "memory")
#define CP_COMMIT() asm volatile("cp.async.commit_group;" ::: "memory")
#define CP_WAIT0()  asm volatile("cp.async.wait_group 0;" ::: "memory")
#define CP_WAIT1()  asm volatile("cp.async.wait_group 1;" ::: "memory")

#define LDSM_X4(d0, d1, d2, d3, addr)                                          \
    asm volatile("ldmatrix.sync.aligned.m8n8.x4.shared.b16 {%0,%1,%2,%3}, [%4];" \
        : "=r"(d0), "=r"(d1), "=r"(d2), "=r"(d3) : "r"(addr))
#define LDSM_X4_T(d0, d1, d2, d3, addr)                                        \
    asm volatile("ldmatrix.sync.aligned.m8n8.x4.trans.shared.b16 {%0,%1,%2,%3}, [%4];" \
        : "=r"(d0), "=r"(d1), "=r"(d2), "=r"(d3) : "r"(addr))

__device__ __forceinline__ void mma_f16(float* c, uint32_t a0, uint32_t a1,
                                        uint32_t a2, uint32_t a3,
                                        uint32_t b0, uint32_t b1) {
    asm volatile(
        "mma.sync.aligned.m16n8k16.row.col.f32.f16.f16.f32 "
        "{%0,%1,%2,%3}, {%4,%5,%6,%7}, {%8,%9}, {%0,%1,%2,%3};"
        : "+f"(c[0]), "+f"(c[1]), "+f"(c[2]), "+f"(c[3])
        : "r"(a0), "r"(a1), "r"(a2), "r"(a3), "r"(b0), "r"(b1));
}
__device__ __forceinline__ float gelu_f(float v) {
    float u = GELU_C * (v + 0.044715f * v * v * v);
    u = fminf(fmaxf(u, -15.f), 15.f);
    float t = __expf(2.0f * u);
    return 0.5f * v * (1.0f + (t - 1.0f) / (t + 1.0f));
}

// ================= fp16 mma GEMM: BK=64, 2-stage, occ-2 (exact R12/R16) =================
#define KPA 72
#define BPB 136
#define ASTG (128 * KPA)
#define BSTG (64 * BPB)
#define GSM_BYTES (2 * (ASTG + BSTG) * 2)   // 71680 bytes

template <int EPI>
__global__ void __launch_bounds__(256, 2) gemm_h(
    const __half* __restrict__ A, const __half* __restrict__ B, void* __restrict__ Cv,
    int Kd, int lda, int ldb, int ldc,
    const float* __restrict__ bias, const float* __restrict__ modv, int goff,
    const void* __restrict__ en, const float* __restrict__ basep)
{
    extern __shared__ __half smh[];
    const uint32_t smw = smem_u32(smh);

    const int tid = threadIdx.x;
    const int lane = tid & 31;
    const int wid = tid >> 5;
    const int wm = wid >> 2, wn = wid & 3;
    const int lq = lane >> 2, lr = lane & 3;
    const int rsel = lane & 15;
    const int ksel = (lane >> 4) * 8;

    const int row0 = blockIdx.y * 128, col0 = blockIdx.x * 128;

    float acc[4][4][4];
    #pragma unroll
    for (int i = 0; i < 4; i++)
        #pragma unroll
        for (int j = 0; j < 4; j++)
            #pragma unroll
            for (int e = 0; e < 4; e++) acc[i][j][e] = 0.f;

    const int nk = Kd / 64;

    auto load_stage = [&](int ks) {
        const int k0 = ks * 64;
        const int s = ks & 1;
        uint32_t abase = smw + (uint32_t)s * ASTG * 2;
        #pragma unroll
        for (int j = 0; j < 4; j++) {
            int idx = tid + 256 * j;
            int r = idx >> 3, c = idx & 7;
            CP_ASYNC16(abase + (uint32_t)(r * KPA + c * 8) * 2,
                       A + (size_t)(row0 + r) * lda + k0 + c * 8);
        }
        uint32_t bbase = smw + (uint32_t)(2 * ASTG + s * BSTG) * 2;
        #pragma unroll
        for (int j = 0; j < 4; j++) {
            int idx = tid + 256 * j;
            int r = idx >> 4, c = idx & 15;
            CP_ASYNC16(bbase + (uint32_t)(r * BPB + c * 8) * 2,
                       B + (size_t)(k0 + r) * ldb + col0 + c * 8);
        }
        CP_COMMIT();
    };

    load_stage(0);
    if (nk > 1) load_stage(1);

    for (int i = 0; i < nk; i++) {
        if (i == nk - 1) CP_WAIT0(); else CP_WAIT1();
        __syncthreads();

        const int s = i & 1;
        const uint32_t abase = smw + (uint32_t)s * ASTG * 2;
        const uint32_t bbase = smw + (uint32_t)(2 * ASTG + s * BSTG) * 2;

        #pragma unroll
        for (int kt = 0; kt < 4; kt++) {
            uint32_t af[4][4];
            #pragma unroll
            for (int mi = 0; mi < 4; mi++) {
                int rm = wm * 64 + mi * 16;
                LDSM_X4(af[mi][0], af[mi][1], af[mi][2], af[mi][3],
                        abase + (uint32_t)((rm + rsel) * KPA + kt * 16 + ksel) * 2);
            }
            #pragma unroll
            for (int njp = 0; njp < 2; njp++) {
                uint32_t b0, b1, b2, b3;
                int n0 = wn * 32 + njp * 16;
                LDSM_X4_T(b0, b1, b2, b3,
                          bbase + (uint32_t)((kt * 16 + rsel) * BPB + n0 + ksel) * 2);
                #pragma unroll
                for (int mi = 0; mi < 4; mi++) {
                    mma_f16(acc[mi][2 * njp],     af[mi][0], af[mi][1], af[mi][2], af[mi][3], b0, b1);
                    mma_f16(acc[mi][2 * njp + 1], af[mi][0], af[mi][1], af[mi][2], af[mi][3], b2, b3);
                }
            }
        }
        __syncthreads();
        if (i + 2 < nk) load_stage(i + 2);
    }

    #pragma unroll
    for (int mi = 0; mi < 4; mi++) {
        int rg = row0 + wm * 64 + mi * 16 + lq;
        float g0 = 0.f, g1 = 0.f;
        if (EPI == 2) {
            int e0 = g_enIsByte ? (int)((const unsigned char*)en)[rg] : ((const int*)en)[rg];
            int e1 = g_enIsByte ? (int)((const unsigned char*)en)[rg + 8] : ((const int*)en)[rg + 8];
            g0 = e0 ? 1.f : 0.f;
            g1 = e1 ? 1.f : 0.f;
        }
        #pragma unroll
        for (int nj = 0; nj < 4; nj++) {
            int cg = col0 + wn * 32 + nj * 8 + lr * 2;
            float v0 = acc[mi][nj][0], v1 = acc[mi][nj][1];
            float v2 = acc[mi][nj][2], v3 = acc[mi][nj][3];
            if (EPI == 0) {
                __half* C = (__half*)Cv;
                *(half2*)(C + (size_t)rg * ldc + cg) = __floats2half2_rn(v0, v1);
                *(half2*)(C + (size_t)(rg + 8) * ldc + cg) = __floats2half2_rn(v2, v3);
            } else if (EPI == 1) {
                float b0 = bias[cg], b1v = bias[cg + 1];
                __half* C = (__half*)Cv;
                *(half2*)(C + (size_t)rg * ldc + cg) =
                    __floats2half2_rn(gelu_f(v0 + b0), gelu_f(v1 + b1v));
                *(half2*)(C + (size_t)(rg + 8) * ldc + cg) =
                    __floats2half2_rn(gelu_f(v2 + b0), gelu_f(v3 + b1v));
            } else {
                float b0 = bias ? bias[cg] : 0.f, b1v = bias ? bias[cg + 1] : 0.f;
                int bb0 = rg >> 10, bb1 = (rg + 8) >> 10;
                float m00 = modv[bb0 * SIXD + goff + cg];
                float m01 = modv[bb0 * SIXD + goff + cg + 1];
                float m10 = modv[bb1 * SIXD + goff + cg];
                float m11 = modv[bb1 * SIXD + goff + cg + 1];
                float* C = (float*)Cv;
                *(float2*)(C + (size_t)rg * ldc + cg) = make_float2(
                    basep[(size_t)rg * DD + cg] + g0 * m00 * (v0 + b0),
                    basep[(size_t)rg * DD + cg + 1] + g0 * m01 * (v1 + b1v));
                *(float2*)(C + (size_t)(rg + 8) * ldc + cg) = make_float2(
                    basep[(size_t)(rg + 8) * DD + cg] + g1 * m10 * (v2 + b0),
                    basep[(size_t)(rg + 8) * DD + cg + 1] + g1 * m11 * (v3 + b1v));
            }
        }
    }
}

// ================= flash attention (fp16 mma, fused RoPE, occ-2) — exact R16 =================
#define FQP 72
#define FPP 136
#define FKO 9216
#define FVO 18432
#define FPO 27648
#define FL_GRPQ 45056
#define FL_GRPK 45312
#define FL_BYTES (FL_GRPK * 2 + 4096)   // 94720

__global__ void __launch_bounds__(256, 2) flash_h(
    const __half* __restrict__ q, const __half* __restrict__ kv,
    const int* __restrict__ grp, __half* __restrict__ attn,
    const float* __restrict__ cosq, const float* __restrict__ sinq,
    const float* __restrict__ cosk, const float* __restrict__ sink)
{
    extern __shared__ __half smh[];
    const uint32_t smw = smem_u32(smh);
    int* grpq = (int*)(smh + FL_GRPQ);
    int* grpkAll = (int*)(smh + FL_GRPK);

    const int tid = threadIdx.x;
    const int lane = tid & 31;
    const int wid = tid >> 5;
    const int wr0 = wid * 16;
    const int lq = lane >> 2, lr = lane & 3;
    const int rsel = lane & 15;
    const int ksel = (lane >> 4) * 8;
    const int nsel = (lane & 7) + (lane >> 4) * 8;
    const int kse2 = ((lane >> 3) & 1) * 8;

    const int qb = blockIdx.x;
    const int b = blockIdx.y >> 4;
    const int h = blockIdx.y & 15;

    #pragma unroll
    for (int j = 0; j < 4; j++) {
        int idx = tid + 256 * j;
        int r = idx >> 3, c8 = idx & 7;
        int s = qb * 128 + r;
        const __half* row = q + (size_t)(b * SS + s) * DD + h * HD;
        uint4 own = *(const uint4*)(row + 8 * c8);
        uint4 par = *(const uint4*)(row + 8 * (c8 ^ 4));
        const __half* oh = (const __half*)&own;
        const __half* ph = (const __half*)&par;
        float4 cz0 = *(const float4*)(cosq + s * HD + 8 * c8);
        float4 cz1 = *(const float4*)(cosq + s * HD + 8 * c8 + 4);
        float4 sz0 = *(const float4*)(sinq + s * HD + 8 * c8);
        float4 sz1 = *(const float4*)(sinq + s * HD + 8 * c8 + 4);
        float czv[8] = {cz0.x, cz0.y, cz0.z, cz0.w, cz1.x, cz1.y, cz1.z, cz1.w};
        float szv[8] = {sz0.x, sz0.y, sz0.z, sz0.w, sz1.x, sz1.y, sz1.z, sz1.w};
        float sgn = (c8 & 4) ? 1.f : -1.f;
        __half res[8];
        #pragma unroll
        for (int e = 0; e < 8; e++) {
            float x1 = __half2float(oh[e]);
            float x2 = __half2float(ph[e]);
            res[e] = __float2half_rn(x1 * czv[e] + sgn * x2 * szv[e]);
        }
        *(uint4*)(smh + r * FQP + 8 * c8) = *(uint4*)res;
    }
    if (tid < 128) grpq[tid] = grp[b * 1024 + qb * 128 + tid];
    #pragma unroll
    for (int j = 0; j < 4; j++)
        grpkAll[tid + 256 * j] = grp[b * 1024 + tid + 256 * j];

    float m0 = -3.0e38f, m1 = -3.0e38f, l0 = 0.f, l1 = 0.f;
    float oacc[8][4];
    #pragma unroll
    for (int j = 0; j < 8; j++)
        #pragma unroll
        for (int e = 0; e < 4; e++) oacc[j][e] = 0.f;

    for (int kc = 0; kc < 8; kc++) {
        const int* grpk = grpkAll + kc * 128;
        #pragma unroll
        for (int j = 0; j < 4; j++) {
            int idx = tid + 256 * j;
            int r = idx >> 3, c = idx & 7;
            CP_ASYNC16(smw + (uint32_t)(FVO + r * FQP + c * 8) * 2,
                       kv + (size_t)(b * 1024 + kc * 128 + r) * (2 * DD) + DD + h * HD + c * 8);
        }
        CP_COMMIT();
        #pragma unroll
        for (int j = 0; j < 4; j++) {
            int idx = tid + 256 * j;
            int r = idx >> 3, c8 = idx & 7;
            int s = kc * 128 + r;
            const __half* row = kv + (size_t)(b * 1024 + s) * (2 * DD) + h * HD;
            uint4 own = *(const uint4*)(row + 8 * c8);
            uint4 par = *(const uint4*)(row + 8 * (c8 ^ 4));
            const __half* oh = (const __half*)&own;
            const __half* ph = (const __half*)&par;
            float4 cz0 = *(const float4*)(cosk + s * HD + 8 * c8);
            float4 cz1 = *(const float4*)(cosk + s * HD + 8 * c8 + 4);
            float4 sz0 = *(const float4*)(sink + s * HD + 8 * c8);
            float4 sz1 = *(const float4*)(sink + s * HD + 8 * c8 + 4);
            float czv[8] = {cz0.x, cz0.y, cz0.z, cz0.w, cz1.x, cz1.y, cz1.z, cz1.w};
            float szv[8] = {sz0.x, sz0.y, sz0.z, sz0.w, sz1.x, sz1.y, sz1.z, sz1.w};
            float sgn = (c8 & 4) ? 1.f : -1.f;
            __half res[8];
            #pragma unroll
            for (int e = 0; e < 8; e++) {
                float x1 = __half2float(oh[e]);
                float x2 = __half2float(ph[e]);
                res[e] = __float2half_rn(x1 * czv[e] + sgn * x2 * szv[e]);
            }
            *(uint4*)(smh + FKO + r * FQP + 8 * c8) = *(uint4*)res;
        }
        CP_WAIT0();
        __syncthreads();

        float sacc[16][4];
        #pragma unroll
        for (int nj = 0; nj < 16; nj++)
            #pragma unroll
            for (int e = 0; e < 4; e++) sacc[nj][e] = 0.f;

        #pragma unroll
        for (int kt = 0; kt < 4; kt++) {
            uint32_t a0, a1, a2, a3;
            LDSM_X4(a0, a1, a2, a3,
                    smw + (uint32_t)((wr0 + rsel) * FQP + kt * 16 + ksel) * 2);
            #pragma unroll
            for (int njp = 0; njp < 8; njp++) {
                uint32_t b0, b1, b2, b3;
                LDSM_X4(b0, b1, b2, b3,
                        smw + (uint32_t)(FKO + (njp * 16 + nsel) * FQP + kt * 16 + kse2) * 2);
                mma_f16(sacc[2 * njp],     a0, a1, a2, a3, b0, b1);
                mma_f16(sacc[2 * njp + 1], a0, a1, a2, a3, b2, b3);
            }
        }

        int gq0 = grpq[wr0 + lq], gq1 = grpq[wr0 + lq + 8];
        float rm0 = -3.0e38f, rm1 = -3.0e38f;
        #pragma unroll
        for (int nj = 0; nj < 16; nj++) {
            int c0i = nj * 8 + 2 * lr;
            int gk0 = grpk[c0i], gk1 = grpk[c0i + 1];
            float s0 = (gk0 != gq0) ? sacc[nj][0] * INV_SQRT_HD : -1.0e9f;
            float s1 = (gk1 != gq0) ? sacc[nj][1] * INV_SQRT_HD : -1.0e9f;
            float s2 = (gk0 != gq1) ? sacc[nj][2] * INV_SQRT_HD : -1.0e9f;
            float s3 = (gk1 != gq1) ? sacc[nj][3] * INV_SQRT_HD : -1.0e9f;
            sacc[nj][0] = s0; sacc[nj][1] = s1; sacc[nj][2] = s2; sacc[nj][3] = s3;
            rm0 = fmaxf(rm0, fmaxf(s0, s1));
            rm1 = fmaxf(rm1, fmaxf(s2, s3));
        }
        rm0 = fmaxf(rm0, __shfl_xor_sync(0xffffffffu, rm0, 1));
        rm0 = fmaxf(rm0, __shfl_xor_sync(0xffffffffu, rm0, 2));
        rm1 = fmaxf(rm1, __shfl_xor_sync(0xffffffffu, rm1, 1));
        rm1 = fmaxf(rm1, __shfl_xor_sync(0xffffffffu, rm1, 2));
        float mn0 = fmaxf(m0, rm0), mn1 = fmaxf(m1, rm1);
        float al0 = __expf(m0 - mn0), al1 = __expf(m1 - mn1);

        __half* Ps = smh + FPO;
        float ps0 = 0.f, ps1 = 0.f;
        #pragma unroll
        for (int nj = 0; nj < 16; nj++) {
            float e0 = __expf(sacc[nj][0] - mn0);
            float e1 = __expf(sacc[nj][1] - mn0);
            float e2 = __expf(sacc[nj][2] - mn1);
            float e3 = __expf(sacc[nj][3] - mn1);
            ps0 += e0 + e1; ps1 += e2 + e3;
            int c0i = nj * 8 + 2 * lr;
            *(half2*)(Ps + (wr0 + lq) * FPP + c0i) = __floats2half2_rn(e0, e1);
            *(half2*)(Ps + (wr0 + lq + 8) * FPP + c0i) = __floats2half2_rn(e2, e3);
        }
        ps0 += __shfl_xor_sync(0xffffffffu, ps0, 1);
        ps0 += __shfl_xor_sync(0xffffffffu, ps0, 2);
        ps1 += __shfl_xor_sync(0xffffffffu, ps1, 1);
        ps1 += __shfl_xor_sync(0xffffffffu, ps1, 2);
        l0 = l0 * al0 + ps0;
        l1 = l1 * al1 + ps1;
        m0 = mn0; m1 = mn1;

        #pragma unroll
        for (int nj = 0; nj < 8; nj++) {
            oacc[nj][0] *= al0; oacc[nj][1] *= al0;
            oacc[nj][2] *= al1; oacc[nj][3] *= al1;
        }
        __syncwarp();

        #pragma unroll
        for (int kt = 0; kt < 8; kt++) {
            uint32_t a0, a1, a2, a3;
            LDSM_X4(a0, a1, a2, a3,
                    smw + (uint32_t)(FPO + (wr0 + rsel) * FPP + kt * 16 + ksel) * 2);
            #pragma unroll
            for (int njp = 0; njp < 4; njp++) {
                uint32_t b0, b1, b2, b3;
                LDSM_X4_T(b0, b1, b2, b3,
                          smw + (uint32_t)(FVO + (kt * 16 + rsel) * FQP + njp * 16 + ksel) * 2);
                mma_f16(oacc[2 * njp],     a0, a1, a2, a3, b0, b1);
                mma_f16(oacc[2 * njp + 1], a0, a1, a2, a3, b2, b3);
            }
        }
        __syncthreads();
    }

    float il0 = 1.0f / l0, il1 = 1.0f / l1;
    int r0 = b * 1024 + qb * 128 + wr0 + lq;
    #pragma unroll
    for (int nj = 0; nj < 8; nj++) {
        int cg = h * HD + nj * 8 + 2 * lr;
        *(half2*)(attn + (size_t)r0 * DD + cg) =
            __floats2half2_rn(oacc[nj][0] * il0, oacc[nj][1] * il0);
        *(half2*)(attn + (size_t)(r0 + 8) * DD + cg) =
            __floats2half2_rn(oacc[nj][2] * il1, oacc[nj][3] * il1);
    }
}

// ================= small kernels =================
__global__ void __launch_bounds__(256) mod2_k(const float* __restrict__ t_cond,
                                              const float* __restrict__ adaW,
                                              const float* __restrict__ adab,
                                              float* __restrict__ mod,
                                              const int* __restrict__ en32) {
    if (blockIdx.x == 96) {
        __shared__ int shd[8];
        int f = 0;
        #pragma unroll
        for (int j = 0; j < 4; j++) {
            int v = en32[threadIdx.x * 4 + j];
            f |= (v & ~1) ? 1 : 0;
        }
        #pragma unroll
        for (int o = 16; o; o >>= 1) f |= __shfl_xor_sync(0xffffffffu, f, o);
        if ((threadIdx.x & 31) == 0) shd[threadIdx.x >> 5] = f;
        __syncthreads();
        if (threadIdx.x == 0) {
            int t = 0;
            #pragma unroll
            for (int i = 0; i < 8; i++) t |= shd[i];
            g_enIsByte = t;
        }
        return;
    }
    __shared__ float tc[4][1024];
    __shared__ float part[4][4][64];
    for (int i = threadIdx.x; i < 4096; i += 256)
        tc[i >> 10][i & 1023] = t_cond[i];
    __syncthreads();
    const int cc = blockIdx.x * 64;
    const int c = threadIdx.x & 63, kq = threadIdx.x >> 6;
    float a0 = 0.f, a1 = 0.f, a2 = 0.f, a3 = 0.f;
    const int kb = kq * 256;
    #pragma unroll 4
    for (int k = kb; k < kb + 256; k++) {
        float w = adaW[(size_t)k * SIXD + cc + c];
        a0 = fmaf(tc[0][k], w, a0);
        a1 = fmaf(tc[1][k], w, a1);
        a2 = fmaf(tc[2][k], w, a2);
        a3 = fmaf(tc[3][k], w, a3);
    }
    part[kq][0][c] = a0; part[kq][1][c] = a1;
    part[kq][2][c] = a2; part[kq][3][c] = a3;
    __syncthreads();
    if (kq < 4 && threadIdx.x < 64) {
        #pragma unroll
        for (int b = 0; b < 4; b++) {
            float s = part[0][b][c] + part[1][b][c] + part[2][b][c] + part[3][b][c];
            mod[b * SIXD + cc + c] = s + adab[cc + c];
        }
    }
}

__global__ void __launch_bounds__(256) wcvt_all_k(
    const float* __restrict__ s0, __half* __restrict__ d0,
    const float* __restrict__ s1, __half* __restrict__ d1,
    const float* __restrict__ s2, __half* __restrict__ d2,
    const float* __restrict__ s3, __half* __restrict__ d3,
    const float* __restrict__ s4, __half* __restrict__ d4)
{
    int bx = blockIdx.x;
    const float* src; __half* dst; int off;
    if (bx < 256)       { src = s0; dst = d0; off = bx; }
    else if (bx < 768)  { src = s1; dst = d1; off = bx - 256; }
    else if (bx < 1024) { src = s2; dst = d2; off = bx - 768; }
    else if (bx < 2048) { src = s3; dst = d3; off = bx - 1024; }
    else                { src = s4; dst = d4; off = bx - 2048; }
    size_t base = ((size_t)off * 256 + threadIdx.x) * 16;
    #pragma unroll
    for (int j = 0; j < 4; j++) {
        float4 v = *(const float4*)(src + base + 4 * j);
        half2* d = (half2*)(dst + base + 4 * j);
        d[0] = __floats2half2_rn(v.x, v.y);
        d[1] = __floats2half2_rn(v.z, v.w);
    }
}

__device__ __forceinline__ void ln_row_body(const float* __restrict__ xr,
                                            const float* __restrict__ w,
                                            const float* __restrict__ mod,
                                            int b, int shOff, int scOff, int useMod,
                                            __half* __restrict__ orow, float* sh) {
    int tid = threadIdx.x;
    float v[4];
    float s = 0.f, s2 = 0.f;
    #pragma unroll
    for (int j = 0; j < 4; j++) {
        v[j] = xr[tid + j * 256];
        s += v[j];
        s2 = fmaf(v[j], v[j], s2);
    }
    #pragma unroll
    for (int o = 16; o; o >>= 1) {
        s  += __shfl_xor_sync(0xffffffffu, s, o);
        s2 += __shfl_xor_sync(0xffffffffu, s2, o);
    }
    if ((tid & 31) == 0) { sh[tid >> 5] = s; sh[8 + (tid >> 5)] = s2; }
    __syncthreads();
    if (tid == 0) {
        float t = 0.f, t2 = 0.f;
        #pragma unroll
        for (int i = 0; i < 8; i++) { t += sh[i]; t2 += sh[8 + i]; }
        sh[16] = t; sh[17] = t2;
    }
    __syncthreads();
    float mu = sh[16] * (1.0f / DD);
    float var = sh[17] * (1.0f / DD) - mu * mu;
    float rs = rsqrtf(var + 1e-5f);
    #pragma unroll
    for (int j = 0; j < 4; j++) {
        int d = tid + j * 256;
        float y = (v[j] - mu) * rs * w[d];
        if (useMod) y = y * (1.0f + mod[b * SIXD + scOff + d]) + mod[b * SIXD + shOff + d];
        orow[d] = __float2half_rn(y);
    }
}

// generic LN: useMod selects adaLN path
__global__ void __launch_bounds__(256) ln_k(const float* __restrict__ x,
                                            const float* __restrict__ w,
                                            const float* __restrict__ mod,
                                            int shOff, int scOff, int useMod,
                                            __half* __restrict__ out) {
    __shared__ float sh[18];
    int row = blockIdx.x;
    int b = row >> 10;
    ln_row_body(x + (size_t)row * DD, w, mod, b, shOff, scOff, useMod,
                out + (size_t)row * DD, sh);
}

// ================= host =================
extern "C" void kernel_launch(void* const* d_in, const int* in_sizes, int n_in,
                              void* d_out, int out_size) {
    const float* q_x    = (const float*)d_in[0];
    const float* kv_x   = (const float*)d_in[1];
    const float* t_cond = (const float*)d_in[2];
    const float* cos_q  = (const float*)d_in[3];
    const float* sin_q  = (const float*)d_in[4];
    const float* cos_k  = (const float*)d_in[5];
    const float* sin_k  = (const float*)d_in[6];
    const int*   grp    = (const int*)d_in[7];
    const void*  en     = d_in[8];
    const float* qn_w   = (const float*)d_in[9];
    const float* kvn_w  = (const float*)d_in[10];
    const float* n2_w   = (const float*)d_in[11];
    const float* Wq     = (const float*)d_in[12];
    const float* Wkv    = (const float*)d_in[13];
    const float* Wo     = (const float*)d_in[14];
    const float* W1     = (const float*)d_in[15];
    const float* b1     = (const float*)d_in[16];
    const float* W2     = (const float*)d_in[17];
    const float* b2     = (const float*)d_in[18];
    const float* adaW   = (const float*)d_in[19];
    const float* adab   = (const float*)d_in[20];
    float* out = (float*)d_out;

    float *mod, *x;
    __half *qn_h, *kvn_h, *q_h, *kv_h, *attn_h, *hh, *h1_h;
    __half *wq_h, *wkv_h, *wo_h, *w1_h, *w2_h;
    cudaGetSymbolAddress((void**)&mod,    g_mod);
    cudaGetSymbolAddress((void**)&x,      g_x);
    cudaGetSymbolAddress((void**)&qn_h,   g_qn_h);
    cudaGetSymbolAddress((void**)&kvn_h,  g_kvn_h);
    cudaGetSymbolAddress((void**)&q_h,    g_q_h);
    cudaGetSymbolAddress((void**)&kv_h,   g_kv_h);
    cudaGetSymbolAddress((void**)&attn_h, g_attn_h);
    cudaGetSymbolAddress((void**)&hh,     g_hh);
    cudaGetSymbolAddress((void**)&h1_h,   g_h1_h);
    cudaGetSymbolAddress((void**)&wq_h,   g_wq_h);
    cudaGetSymbolAddress((void**)&wkv_h,  g_wkv_h);
    cudaGetSymbolAddress((void**)&wo_h,   g_wo_h);
    cudaGetSymbolAddress((void**)&w1_h,   g_w1_h);
    cudaGetSymbolAddress((void**)&w2_h,   g_w2_h);

    cudaFuncSetAttribute(gemm_h<0>, cudaFuncAttributeMaxDynamicSharedMemorySize, GSM_BYTES);
    cudaFuncSetAttribute(gemm_h<1>, cudaFuncAttributeMaxDynamicSharedMemorySize, GSM_BYTES);
    cudaFuncSetAttribute(gemm_h<2>, cudaFuncAttributeMaxDynamicSharedMemorySize, GSM_BYTES);
    cudaFuncSetAttribute(flash_h, cudaFuncAttributeMaxDynamicSharedMemorySize, FL_BYTES);

    static cudaStream_t s1 = nullptr;
    static cudaEvent_t eva = nullptr, evq = nullptr, evw = nullptr;
    static int sinit = 0;
    if (sinit == 0) {
        if (cudaStreamCreateWithFlags(&s1, cudaStreamNonBlocking) == cudaSuccess &&
            cudaEventCreateWithFlags(&eva, cudaEventDisableTiming) == cudaSuccess &&
            cudaEventCreateWithFlags(&evq, cudaEventDisableTiming) == cudaSuccess &&
            cudaEventCreateWithFlags(&evw, cudaEventDisableTiming) == cudaSuccess)
            sinit = 1;
        else
            sinit = -1;
    }
    const bool useStreams = (sinit == 1);

    if (useStreams) {
        // fork: s1 handles weight convert + mod + q-chain; default handles kv-chain.
        cudaEventRecord(eva, 0);
        cudaStreamWaitEvent(s1, eva, 0);

        // s1: wcvt -> mod2(+en detect) -> q-LN -> Wq GEMM
        wcvt_all_k<<<3072, 256, 0, s1>>>(Wq, wq_h, Wkv, wkv_h, Wo, wo_h, W1, w1_h, W2, w2_h);
        cudaEventRecord(evw, s1);   // weights ready (for Wkv on default)
        mod2_k<<<97, 256, 0, s1>>>(t_cond, adaW, adab, mod, (const int*)en);
        ln_k<<<NBS, 256, 0, s1>>>(q_x, qn_w, mod, 0, DD, 1, qn_h);
        gemm_h<0><<<dim3(8, 32), 256, GSM_BYTES, s1>>>(
            qn_h, wq_h, q_h, DD, DD, DD, DD, nullptr, nullptr, 0, nullptr, nullptr);
        cudaEventRecord(evq, s1);

        // default: kv-LN (independent) -> wait weights -> Wkv GEMM
        ln_k<<<NBS, 256>>>(kv_x, kvn_w, mod, 0, 0, 0, kvn_h);
        cudaStreamWaitEvent(0, evw, 0);
        gemm_h<0><<<dim3(16, 32), 256, GSM_BYTES>>>(
            kvn_h, wkv_h, kv_h, DD, DD, 2 * DD, 2 * DD, nullptr, nullptr, 0, nullptr, nullptr);
        cudaStreamWaitEvent(0, evq, 0);   // join q-chain (also orders mod/en for later)
    } else {
        wcvt_all_k<<<3072, 256>>>(Wq, wq_h, Wkv, wkv_h, Wo, wo_h, W1, w1_h, W2, w2_h);
        mod2_k<<<97, 256>>>(t_cond, adaW, adab, mod, (const int*)en);
        ln_k<<<NBS, 256>>>(q_x, qn_w, mod, 0, DD, 1, qn_h);
        ln_k<<<NBS, 256>>>(kv_x, kvn_w, mod, 0, 0, 0, kvn_h);
        gemm_h<0><<<dim3(8, 32), 256, GSM_BYTES>>>(
            qn_h, wq_h, q_h, DD, DD, DD, DD, nullptr, nullptr, 0, nullptr, nullptr);
        gemm_h<0><<<dim3(16, 32), 256, GSM_BYTES>>>(
            kvn_h, wkv_h, kv_h, DD, DD, 2 * DD, 2 * DD, nullptr, nullptr, 0, nullptr, nullptr);
    }

    flash_h<<<dim3(SS / 128, BB * HH), 256, FL_BYTES>>>(
        q_h, kv_h, grp, attn_h, cos_q, sin_q, cos_k, sin_k);

    gemm_h<2><<<dim3(8, 32), 256, GSM_BYTES>>>(
        attn_h, wo_h, x, DD, DD, DD, DD, nullptr, mod, 2 * DD, en, q_x);

    ln_k<<<NBS, 256>>>(x, n2_w, mod, 3 * DD, 4 * DD, 1, hh);

    gemm_h<1><<<dim3(32, 32), 256, GSM_BYTES>>>(
        hh, w1_h, h1_h, DD, DD, MRD, MRD, b1, nullptr, 0, nullptr, nullptr);
    gemm_h<2><<<dim3(8, 32), 256, GSM_BYTES>>>(
        h1_h, w2_h, out, MRD, MRD, DD, DD, b2, mod, 5 * DD, en, x);
}